// round 1
// baseline (speedup 1.0000x reference)
#include <cuda_runtime.h>
#include <math.h>

// Problem dims
#define Bb   1024
#define Tt   32
#define Xs   128
#define Asz  128
#define XHd  512
#define AHd  512
#define Dd   1152
#define G3   1536
#define NSTEP 31

// ---------------- scratch (device globals; no allocation) ----------------
__device__ float g_s   [Bb * Dd];     // state: [z_x | z_a | x]
__device__ float g_cat [Bb * 256];    // [xt | a_t]
__device__ float g_mask[Bb];
__device__ float g_gia [Bb * G3];
__device__ float g_gha [Bb * G3];
__device__ float g_gix [Bb * G3];
__device__ float g_ghx [Bb * G3];
__device__ float g_hbuf[Bb * Dd];     // softplus output
__device__ float g_k1  [Bb * Dd];
__device__ float g_k2  [Bb * Dd];
__device__ float g_k3  [Bb * Dd];
__device__ float g_k4  [Bb * Dd];
__device__ float g_accb[Bb * Dd];
__device__ float g_arg [Bb * Dd];

__device__ __forceinline__ float sigm(float x) { return 1.0f / (1.0f + expf(-x)); }

// ---------------- GEMM: C[M,N] = act(A[M,K] @ W[N,K]^T + bias[N]) --------
// 64x64 tile, BK=16, 256 threads, 4x4 per thread. All dims multiples of 64/16.
__global__ void __launch_bounds__(256) sgemm_bias(
    const float* __restrict__ A, int lda,
    const float* __restrict__ W, int ldw,
    const float* __restrict__ bias,
    float* __restrict__ C, int ldc,
    int K, int act)
{
    __shared__ float As[16][64];
    __shared__ float Ws[16][64];

    int tid  = threadIdx.x;
    int row4 = tid >> 2;          // 0..63
    int kq   = (tid & 3) * 4;     // 0,4,8,12
    const float* Ag = A + (size_t)(blockIdx.y * 64 + row4) * lda + kq;
    const float* Wg = W + (size_t)(blockIdx.x * 64 + row4) * ldw + kq;

    int tx = tid & 15, ty = tid >> 4;
    float acc[4][4] = {};

    for (int kt = 0; kt < K; kt += 16) {
        float4 av = *(const float4*)(Ag + kt);
        float4 wv = *(const float4*)(Wg + kt);
        As[kq + 0][row4] = av.x; As[kq + 1][row4] = av.y;
        As[kq + 2][row4] = av.z; As[kq + 3][row4] = av.w;
        Ws[kq + 0][row4] = wv.x; Ws[kq + 1][row4] = wv.y;
        Ws[kq + 2][row4] = wv.z; Ws[kq + 3][row4] = wv.w;
        __syncthreads();
#pragma unroll
        for (int k = 0; k < 16; k++) {
            float4 a = *(const float4*)&As[k][ty * 4];
            float4 b = *(const float4*)&Ws[k][tx * 4];
            float ar[4] = {a.x, a.y, a.z, a.w};
            float br[4] = {b.x, b.y, b.z, b.w};
#pragma unroll
            for (int i = 0; i < 4; i++)
#pragma unroll
                for (int j = 0; j < 4; j++)
                    acc[i][j] += ar[i] * br[j];
        }
        __syncthreads();
    }

    int crow = blockIdx.y * 64 + ty * 4;
    int ccol = blockIdx.x * 64 + tx * 4;
    float4 bv = *(const float4*)(bias + ccol);
    float bb[4] = {bv.x, bv.y, bv.z, bv.w};
#pragma unroll
    for (int i = 0; i < 4; i++) {
        float4 o;
        float v0 = acc[i][0] + bb[0];
        float v1 = acc[i][1] + bb[1];
        float v2 = acc[i][2] + bb[2];
        float v3 = acc[i][3] + bb[3];
        if (act == 1) {  // softplus = max(x,0)+log1p(exp(-|x|))
            v0 = fmaxf(v0, 0.f) + log1pf(expf(-fabsf(v0)));
            v1 = fmaxf(v1, 0.f) + log1pf(expf(-fabsf(v1)));
            v2 = fmaxf(v2, 0.f) + log1pf(expf(-fabsf(v2)));
            v3 = fmaxf(v3, 0.f) + log1pf(expf(-fabsf(v3)));
        }
        o.x = v0; o.y = v1; o.z = v2; o.w = v3;
        *(float4*)(C + (size_t)(crow + i) * ldc + ccol) = o;
    }
}

// ---------------- elementwise kernels ----------------
// init: s[:, :1024]=0, s[:,1024:]=x[:,0,:]; out_x[:,0,:]=x0; out_za[:,0,:]=0
__global__ void init_k(const float* __restrict__ x, float* __restrict__ out_x,
                       float* __restrict__ out_za)
{
    int idx = blockIdx.x * blockDim.x + threadIdx.x;
    if (idx >= Bb * Dd) return;
    int b = idx / Dd, j = idx % Dd;
    if (j < 1024) {
        g_s[idx] = 0.0f;
        if (j < AHd) out_za[((size_t)b * Tt) * AHd + j] = 0.0f;
    } else {
        float v = x[((size_t)b * Tt) * Xs + (j - 1024)];
        g_s[idx] = v;
        out_x[((size_t)b * Tt) * Xs + (j - 1024)] = v;
    }
}

// build concat [xt | a_t] and mask
__global__ void catmask_k(const float* __restrict__ y, int t)
{
    int b = blockIdx.x;
    int c = threadIdx.x;  // 128
    float yv = y[((size_t)b * Tt + t) * Asz + c];
    g_cat[b * 256 + 128 + c] = yv;
    g_cat[b * 256 + c] = g_s[b * Dd + 1024 + c];
    __shared__ float red[128];
    red[c] = yv;
    __syncthreads();
    for (int o = 64; o > 0; o >>= 1) {
        if (c < o) red[c] += red[c + o];
        __syncthreads();
    }
    if (c == 0) g_mask[b] = (red[0] != 0.0f) ? 1.0f : 0.0f;
}

__global__ void gru_a_k(float* __restrict__ out_za, int t)
{
    int idx = blockIdx.x * blockDim.x + threadIdx.x;
    if (idx >= Bb * AHd) return;
    int b = idx / AHd, j = idx % AHd;
    const float* gi = g_gia + (size_t)b * G3;
    const float* gh = g_gha + (size_t)b * G3;
    float r = sigm(gi[j] + gh[j]);
    float z = sigm(gi[AHd + j] + gh[AHd + j]);
    float n = tanhf(gi[2 * AHd + j] + r * gh[2 * AHd + j]);
    float h = g_s[b * Dd + XHd + j];
    float hn = (1.0f - z) * n + z * h;
    float v = (g_mask[b] != 0.0f) ? hn : h;
    g_s[b * Dd + XHd + j] = v;
    out_za[((size_t)b * Tt + t + 1) * AHd + j] = v;
}

__global__ void gru_x_k()
{
    int idx = blockIdx.x * blockDim.x + threadIdx.x;
    if (idx >= Bb * XHd) return;
    int b = idx / XHd, j = idx % XHd;
    const float* gi = g_gix + (size_t)b * G3;
    const float* gh = g_ghx + (size_t)b * G3;
    float r = sigm(gi[j] + gh[j]);
    float z = sigm(gi[XHd + j] + gh[XHd + j]);
    float n = tanhf(gi[2 * XHd + j] + r * gh[2 * XHd + j]);
    float h = g_s[b * Dd + j];
    g_s[b * Dd + j] = (1.0f - z) * n + z * h;
}

// RK4 combines. dt read from time_steps on device.
__global__ void rk_c1(const float* __restrict__ ts, int t)
{
    int i = blockIdx.x * blockDim.x + threadIdx.x;
    if (i >= Bb * Dd) return;
    float dt = ts[t + 1] - ts[t];
    g_arg[i] = g_s[i] + (dt * (1.0f / 3.0f)) * g_k1[i];
}
__global__ void rk_c2(const float* __restrict__ ts, int t)
{
    int i = blockIdx.x * blockDim.x + threadIdx.x;
    if (i >= Bb * Dd) return;
    float dt = ts[t + 1] - ts[t];
    float k1 = g_k1[i], k2 = g_k2[i];
    g_arg[i]  = g_s[i] + dt * (k2 - k1 * (1.0f / 3.0f));
    g_accb[i] = k1 + 3.0f * k2;
}
__global__ void rk_c3(const float* __restrict__ ts, int t)
{
    int i = blockIdx.x * blockDim.x + threadIdx.x;
    if (i >= Bb * Dd) return;
    float dt = ts[t + 1] - ts[t];
    float k1 = g_k1[i], k2 = g_k2[i], k3 = g_k3[i];
    g_arg[i]  = g_s[i] + dt * (k1 - k2 + k3);
    g_accb[i] = g_accb[i] + 3.0f * k3;
}
__global__ void rk_c4(const float* __restrict__ ts, float* __restrict__ out_x, int t)
{
    int i = blockIdx.x * blockDim.x + threadIdx.x;
    if (i >= Bb * Dd) return;
    float dt = ts[t + 1] - ts[t];
    int b = i / Dd, j = i % Dd;
    float v = g_s[i] + (dt * 0.125f) * (g_accb[i] + g_k4[i]);
    g_s[i] = v;
    if (j >= 1024)
        out_x[((size_t)b * Tt + t + 1) * Xs + (j - 1024)] = v;
}

// ---------------- host ----------------
static inline void gemm(const float* A, int lda, const float* W, int ldw,
                        const float* bias, float* C, int ldc,
                        int M, int N, int K, int act)
{
    dim3 grid(N / 64, M / 64);
    sgemm_bias<<<grid, 256>>>(A, lda, W, ldw, bias, C, ldc, K, act);
}

extern "C" void kernel_launch(void* const* d_in, const int* in_sizes, int n_in,
                              void* d_out, int out_size)
{
    const float* x    = (const float*)d_in[0];
    const float* y    = (const float*)d_in[1];
    const float* ts   = (const float*)d_in[2];
    const float* Wiha = (const float*)d_in[3];
    const float* Whha = (const float*)d_in[4];
    const float* biha = (const float*)d_in[5];
    const float* bhha = (const float*)d_in[6];
    const float* Wihx = (const float*)d_in[7];
    const float* Whhx = (const float*)d_in[8];
    const float* bihx = (const float*)d_in[9];
    const float* bhhx = (const float*)d_in[10];
    const float* W1   = (const float*)d_in[11];
    const float* b1   = (const float*)d_in[12];
    const float* W2   = (const float*)d_in[13];
    const float* b2   = (const float*)d_in[14];

    float* out_x  = (float*)d_out;
    float* out_za = out_x + (size_t)Bb * Tt * Xs;

    float *ps, *pcat, *pgia, *pgha, *pgix, *pghx, *ph, *pk1, *pk2, *pk3, *pk4, *parg;
    cudaGetSymbolAddress((void**)&ps,   g_s);
    cudaGetSymbolAddress((void**)&pcat, g_cat);
    cudaGetSymbolAddress((void**)&pgia, g_gia);
    cudaGetSymbolAddress((void**)&pgha, g_gha);
    cudaGetSymbolAddress((void**)&pgix, g_gix);
    cudaGetSymbolAddress((void**)&pghx, g_ghx);
    cudaGetSymbolAddress((void**)&ph,   g_hbuf);
    cudaGetSymbolAddress((void**)&pk1,  g_k1);
    cudaGetSymbolAddress((void**)&pk2,  g_k2);
    cudaGetSymbolAddress((void**)&pk3,  g_k3);
    cudaGetSymbolAddress((void**)&pk4,  g_k4);
    cudaGetSymbolAddress((void**)&parg, g_arg);

    const int nBD = Bb * Dd;
    const int blkBD = (nBD + 255) / 256;
    const int nBH = Bb * XHd;
    const int blkBH = (nBH + 255) / 256;

    init_k<<<blkBD, 256>>>(x, out_x, out_za);

    for (int t = 0; t < NSTEP; t++) {
        // --- GRU gate GEMMs (read old state) ---
        catmask_k<<<Bb, 128>>>(y, t);
        gemm(pcat,      256, Wiha, 256, biha, pgia, G3, Bb, G3, 256, 0);
        gemm(ps + XHd,  Dd,  Whha, 512, bhha, pgha, G3, Bb, G3, 512, 0);
        gemm(ps + 1024, Dd,  Wihx, 128, bihx, pgix, G3, Bb, G3, 128, 0);
        gemm(ps,        Dd,  Whhx, 512, bhhx, pghx, G3, Bb, G3, 512, 0);
        gru_a_k<<<blkBH, 256>>>(out_za, t);
        gru_x_k<<<blkBH, 256>>>();

        // --- RK4 (3/8 rule) ---
        // k1 = f(s)
        gemm(ps,   Dd, W1, Dd, b1, ph,  Dd, Bb, Dd, Dd, 1);
        gemm(ph,   Dd, W2, Dd, b2, pk1, Dd, Bb, Dd, Dd, 0);
        rk_c1<<<blkBD, 256>>>(ts, t);
        // k2 = f(s + h/3 k1)
        gemm(parg, Dd, W1, Dd, b1, ph,  Dd, Bb, Dd, Dd, 1);
        gemm(ph,   Dd, W2, Dd, b2, pk2, Dd, Bb, Dd, Dd, 0);
        rk_c2<<<blkBD, 256>>>(ts, t);
        // k3 = f(s + h(k2 - k1/3))
        gemm(parg, Dd, W1, Dd, b1, ph,  Dd, Bb, Dd, Dd, 1);
        gemm(ph,   Dd, W2, Dd, b2, pk3, Dd, Bb, Dd, Dd, 0);
        rk_c3<<<blkBD, 256>>>(ts, t);
        // k4 = f(s + h(k1 - k2 + k3))
        gemm(parg, Dd, W1, Dd, b1, ph,  Dd, Bb, Dd, Dd, 1);
        gemm(ph,   Dd, W2, Dd, b2, pk4, Dd, Bb, Dd, Dd, 0);
        rk_c4<<<blkBD, 256>>>(ts, out_x, t);
    }
}

// round 2
// speedup vs baseline: 1.1635x; 1.1635x over previous
#include <cuda_runtime.h>
#include <cuda_bf16.h>
#include <math.h>
#include <stdint.h>

#define Bb   1024
#define Tt   32
#define Xs   128
#define XHd  512
#define AHd  512
#define Dd   1152
#define G3   1536
#define NSTEP 31

// ---------------- fp32 scratch ----------------
__device__ float g_s   [Bb * Dd];
__device__ float g_cat [Bb * 256];
__device__ float g_mask[Bb];
__device__ float g_gia [Bb * G3];
__device__ float g_gha [Bb * G3];
__device__ float g_gix [Bb * G3];
__device__ float g_ghx [Bb * G3];
__device__ float g_k1  [Bb * Dd];
__device__ float g_k2  [Bb * Dd];
__device__ float g_k3  [Bb * Dd];
__device__ float g_k4  [Bb * Dd];
__device__ float g_accb[Bb * Dd];

// ---------------- packed bf16 (split [hi|hi|lo] for A-side, [hi|lo|hi] for B-side) ----------------
__device__ __nv_bfloat16 pk_s  [Bb * 3 * Dd];   // state / RK arg, packed
__device__ __nv_bfloat16 pk_cat[Bb * 3 * 256];
__device__ __nv_bfloat16 pk_h  [Bb * 3 * Dd];   // softplus output packed
__device__ __nv_bfloat16 pw_iha[G3 * 3 * 256];
__device__ __nv_bfloat16 pw_hha[G3 * 3 * 512];
__device__ __nv_bfloat16 pw_ihx[G3 * 3 * 128];
__device__ __nv_bfloat16 pw_hhx[G3 * 3 * 512];
__device__ __nv_bfloat16 pw_1  [Dd * 3 * Dd];
__device__ __nv_bfloat16 pw_2  [Dd * 3 * Dd];

__device__ __forceinline__ float sigm(float x) { return 1.0f / (1.0f + expf(-x)); }
__device__ __forceinline__ float splus(float x) { return fmaxf(x, 0.f) + log1pf(expf(-fabsf(x))); }

// A-side pack: [hi | hi | lo]
__device__ __forceinline__ void packA_el(__nv_bfloat16* rowbase, int K, int k, float v)
{
    __nv_bfloat16 hi = __float2bfloat16(v);
    __nv_bfloat16 lo = __float2bfloat16(v - __bfloat162float(hi));
    rowbase[k] = hi; rowbase[K + k] = hi; rowbase[2 * K + k] = lo;
}

__device__ __forceinline__ void cpa16(void* s, const void* g)
{
    uint32_t sa = (uint32_t)__cvta_generic_to_shared(s);
    asm volatile("cp.async.cg.shared.global [%0], [%1], 16;\n" :: "r"(sa), "l"(g));
}

// ---------------- bf16 split-GEMM: C[M,N] = A'[M,3K] @ B'[N,3K]^T (+bias, epilogue mode) ----
// BM=64, BN=128, BK=32, 256 threads, warps 2x4, warp tile 32x32 via m16n8k16.
// Segment addressing: col(k') = seg*segX + (k' mod K), seg = k'/K.
// mode 0: C fp32, +bias. mode 1: softplus(.+bias) -> packed bf16 [hi|hi|lo], row stride 3K.
__global__ void __launch_bounds__(256, 2) gemm_bf16(
    const __nv_bfloat16* __restrict__ A, int lda, int segA,
    const __nv_bfloat16* __restrict__ B, int ldb, int segB,
    const float* __restrict__ bias,
    void* __restrict__ Cv, int ldc, int K, int mode)
{
    __shared__ __nv_bfloat16 As[2][64][40];
    __shared__ __nv_bfloat16 Bs[2][128][40];

    const int tid = threadIdx.x, lane = tid & 31, wid = tid >> 5;
    const int wm = wid >> 2, wn = wid & 3;
    const int bm = blockIdx.y, bn = blockIdx.x;

    const int arow = tid >> 2, ac8 = (tid & 3) * 8;
    const __nv_bfloat16* Ag  = A + (size_t)(bm * 64 + arow) * lda;
    const __nv_bfloat16* Bg0 = B + (size_t)(bn * 128 + arow) * ldb;
    const __nv_bfloat16* Bg1 = B + (size_t)(bn * 128 + 64 + arow) * ldb;

    const int nk = 3 * K / 32;

    float acc[2][4][4];
#pragma unroll
    for (int i = 0; i < 2; i++)
#pragma unroll
        for (int j = 0; j < 4; j++)
#pragma unroll
            for (int q = 0; q < 4; q++) acc[i][j][q] = 0.f;

#define ISSUE(i, buf)                                                          \
    {                                                                          \
        int kk = (i) * 32;                                                     \
        int seg = (kk >= K) ? ((kk >= 2 * K) ? 2 : 1) : 0;                     \
        int w = kk - seg * K;                                                  \
        int acl = seg * segA + w;                                              \
        int bcl = seg * segB + w;                                              \
        cpa16(&As[buf][arow][ac8],      Ag  + acl + ac8);                      \
        cpa16(&Bs[buf][arow][ac8],      Bg0 + bcl + ac8);                      \
        cpa16(&Bs[buf][64 + arow][ac8], Bg1 + bcl + ac8);                      \
        asm volatile("cp.async.commit_group;\n" ::);                           \
    }

    ISSUE(0, 0)
    for (int i = 0; i < nk; i++) {
        int buf = i & 1;
        if (i + 1 < nk) {
            ISSUE(i + 1, buf ^ 1)
            asm volatile("cp.async.wait_group 1;\n" ::);
        } else {
            asm volatile("cp.async.wait_group 0;\n" ::);
        }
        __syncthreads();

#pragma unroll
        for (int ks = 0; ks < 2; ks++) {
            const int k0 = ks * 16;
            uint32_t a[2][4], b[4][2];
#pragma unroll
            for (int mi = 0; mi < 2; mi++) {
                uint32_t sa = (uint32_t)__cvta_generic_to_shared(
                    &As[buf][wm * 32 + mi * 16 + (lane & 15)][k0 + (lane >> 4) * 8]);
                asm volatile("ldmatrix.sync.aligned.m8n8.x4.shared.b16 {%0,%1,%2,%3}, [%4];"
                             : "=r"(a[mi][0]), "=r"(a[mi][1]), "=r"(a[mi][2]), "=r"(a[mi][3])
                             : "r"(sa));
            }
#pragma unroll
            for (int ni = 0; ni < 4; ni++) {
                uint32_t sb = (uint32_t)__cvta_generic_to_shared(
                    &Bs[buf][wn * 32 + ni * 8 + (lane & 7)][k0 + ((lane >> 3) & 1) * 8]);
                asm volatile("ldmatrix.sync.aligned.m8n8.x2.shared.b16 {%0,%1}, [%2];"
                             : "=r"(b[ni][0]), "=r"(b[ni][1])
                             : "r"(sb));
            }
#pragma unroll
            for (int mi = 0; mi < 2; mi++)
#pragma unroll
                for (int ni = 0; ni < 4; ni++) {
                    asm volatile(
                        "mma.sync.aligned.m16n8k16.row.col.f32.bf16.bf16.f32 "
                        "{%0,%1,%2,%3}, {%4,%5,%6,%7}, {%8,%9}, {%0,%1,%2,%3};"
                        : "+f"(acc[mi][ni][0]), "+f"(acc[mi][ni][1]),
                          "+f"(acc[mi][ni][2]), "+f"(acc[mi][ni][3])
                        : "r"(a[mi][0]), "r"(a[mi][1]), "r"(a[mi][2]), "r"(a[mi][3]),
                          "r"(b[ni][0]), "r"(b[ni][1]));
                }
        }
        __syncthreads();
    }
#undef ISSUE

    const int rbase = bm * 64 + wm * 32;
    const int cbase = bn * 128 + wn * 32;

    if (mode == 0) {
        float* C = (float*)Cv;
#pragma unroll
        for (int mi = 0; mi < 2; mi++)
#pragma unroll
            for (int ni = 0; ni < 4; ni++) {
                int r0 = rbase + mi * 16 + (lane >> 2);
                int c0 = cbase + ni * 8 + (lane & 3) * 2;
                float b0 = bias[c0], b1 = bias[c0 + 1];
                float2 o0 = make_float2(acc[mi][ni][0] + b0, acc[mi][ni][1] + b1);
                float2 o1 = make_float2(acc[mi][ni][2] + b0, acc[mi][ni][3] + b1);
                *(float2*)(C + (size_t)r0 * ldc + c0) = o0;
                *(float2*)(C + (size_t)(r0 + 8) * ldc + c0) = o1;
            }
    } else {
        __nv_bfloat16* C = (__nv_bfloat16*)Cv;  // packed, row stride 3K
#pragma unroll
        for (int mi = 0; mi < 2; mi++)
#pragma unroll
            for (int ni = 0; ni < 4; ni++) {
                int r0 = rbase + mi * 16 + (lane >> 2);
                int c0 = cbase + ni * 8 + (lane & 3) * 2;
                float b0 = bias[c0], b1 = bias[c0 + 1];
#pragma unroll
                for (int h = 0; h < 2; h++) {
                    float v0 = splus(acc[mi][ni][2 * h + 0] + b0);
                    float v1 = splus(acc[mi][ni][2 * h + 1] + b1);
                    __nv_bfloat16 h0 = __float2bfloat16(v0), h1 = __float2bfloat16(v1);
                    __nv_bfloat16 l0 = __float2bfloat16(v0 - __bfloat162float(h0));
                    __nv_bfloat16 l1 = __float2bfloat16(v1 - __bfloat162float(h1));
                    __nv_bfloat162 hh; hh.x = h0; hh.y = h1;
                    __nv_bfloat162 ll; ll.x = l0; ll.y = l1;
                    __nv_bfloat16* base = C + (size_t)(r0 + 8 * h) * (3 * K) + c0;
                    *(__nv_bfloat162*)(base)         = hh;
                    *(__nv_bfloat162*)(base + K)     = hh;
                    *(__nv_bfloat162*)(base + 2 * K) = ll;
                }
            }
    }
}

// ---------------- weight pack (B-side: [hi | lo | hi]) ----------------
__global__ void packW_k(const float* __restrict__ in, __nv_bfloat16* __restrict__ out,
                        int N, int K)
{
    int idx = blockIdx.x * blockDim.x + threadIdx.x;
    if (idx >= N * K) return;
    int n = idx / K, k = idx % K;
    float v = in[(size_t)n * K + k];
    __nv_bfloat16 hi = __float2bfloat16(v);
    __nv_bfloat16 lo = __float2bfloat16(v - __bfloat162float(hi));
    __nv_bfloat16* o = out + (size_t)n * 3 * K;
    o[k] = hi; o[K + k] = lo; o[2 * K + k] = hi;
}

// ---------------- elementwise (all fuse state packing) ----------------
__global__ void init_k(const float* __restrict__ x, float* __restrict__ out_x,
                       float* __restrict__ out_za)
{
    int idx = blockIdx.x * blockDim.x + threadIdx.x;
    if (idx >= Bb * Dd) return;
    int b = idx / Dd, j = idx % Dd;
    float v;
    if (j < 1024) {
        v = 0.0f;
        if (j < AHd) out_za[((size_t)b * Tt) * AHd + j] = 0.0f;
    } else {
        v = x[((size_t)b * Tt) * Xs + (j - 1024)];
        out_x[((size_t)b * Tt) * Xs + (j - 1024)] = v;
    }
    g_s[idx] = v;
    packA_el(pk_s + (size_t)b * 3 * Dd, Dd, j, v);
}

__global__ void catmask_k(const float* __restrict__ y, int t)
{
    int b = blockIdx.x;
    int c = threadIdx.x;  // 128
    float yv = y[((size_t)b * Tt + t) * 128 + c];
    float xv = g_s[b * Dd + 1024 + c];
    g_cat[b * 256 + c] = xv;           // kept for clarity (unused downstream)
    g_cat[b * 256 + 128 + c] = yv;
    __nv_bfloat16* rb = pk_cat + (size_t)b * 768;
    packA_el(rb, 256, c, xv);
    packA_el(rb, 256, 128 + c, yv);
    __shared__ float red[128];
    red[c] = yv;
    __syncthreads();
    for (int o = 64; o > 0; o >>= 1) {
        if (c < o) red[c] += red[c + o];
        __syncthreads();
    }
    if (c == 0) g_mask[b] = (red[0] != 0.0f) ? 1.0f : 0.0f;
}

__global__ void gru_a_k(float* __restrict__ out_za, int t)
{
    int idx = blockIdx.x * blockDim.x + threadIdx.x;
    if (idx >= Bb * AHd) return;
    int b = idx / AHd, j = idx % AHd;
    const float* gi = g_gia + (size_t)b * G3;
    const float* gh = g_gha + (size_t)b * G3;
    float r = sigm(gi[j] + gh[j]);
    float z = sigm(gi[AHd + j] + gh[AHd + j]);
    float n = tanhf(gi[2 * AHd + j] + r * gh[2 * AHd + j]);
    float h = g_s[b * Dd + XHd + j];
    float hn = (1.0f - z) * n + z * h;
    float v = (g_mask[b] != 0.0f) ? hn : h;
    g_s[b * Dd + XHd + j] = v;
    packA_el(pk_s + (size_t)b * 3 * Dd, Dd, XHd + j, v);
    out_za[((size_t)b * Tt + t + 1) * AHd + j] = v;
}

__global__ void gru_x_k()
{
    int idx = blockIdx.x * blockDim.x + threadIdx.x;
    if (idx >= Bb * XHd) return;
    int b = idx / XHd, j = idx % XHd;
    const float* gi = g_gix + (size_t)b * G3;
    const float* gh = g_ghx + (size_t)b * G3;
    float r = sigm(gi[j] + gh[j]);
    float z = sigm(gi[XHd + j] + gh[XHd + j]);
    float n = tanhf(gi[2 * XHd + j] + r * gh[2 * XHd + j]);
    float h = g_s[b * Dd + j];
    float v = (1.0f - z) * n + z * h;
    g_s[b * Dd + j] = v;
    packA_el(pk_s + (size_t)b * 3 * Dd, Dd, j, v);
}

// RK combine kernels: write next GEMM argument straight into pk_s (packed).
__global__ void rk_c1(const float* __restrict__ ts, int t)
{
    int i = blockIdx.x * blockDim.x + threadIdx.x;
    if (i >= Bb * Dd) return;
    float dt = ts[t + 1] - ts[t];
    int b = i / Dd, j = i % Dd;
    float v = g_s[i] + (dt * (1.0f / 3.0f)) * g_k1[i];
    packA_el(pk_s + (size_t)b * 3 * Dd, Dd, j, v);
}
__global__ void rk_c2(const float* __restrict__ ts, int t)
{
    int i = blockIdx.x * blockDim.x + threadIdx.x;
    if (i >= Bb * Dd) return;
    float dt = ts[t + 1] - ts[t];
    int b = i / Dd, j = i % Dd;
    float k1 = g_k1[i], k2 = g_k2[i];
    float v = g_s[i] + dt * (k2 - k1 * (1.0f / 3.0f));
    g_accb[i] = k1 + 3.0f * k2;
    packA_el(pk_s + (size_t)b * 3 * Dd, Dd, j, v);
}
__global__ void rk_c3(const float* __restrict__ ts, int t)
{
    int i = blockIdx.x * blockDim.x + threadIdx.x;
    if (i >= Bb * Dd) return;
    float dt = ts[t + 1] - ts[t];
    int b = i / Dd, j = i % Dd;
    float k1 = g_k1[i], k2 = g_k2[i], k3 = g_k3[i];
    float v = g_s[i] + dt * (k1 - k2 + k3);
    g_accb[i] = g_accb[i] + 3.0f * k3;
    packA_el(pk_s + (size_t)b * 3 * Dd, Dd, j, v);
}
__global__ void rk_c4(const float* __restrict__ ts, float* __restrict__ out_x, int t)
{
    int i = blockIdx.x * blockDim.x + threadIdx.x;
    if (i >= Bb * Dd) return;
    float dt = ts[t + 1] - ts[t];
    int b = i / Dd, j = i % Dd;
    float v = g_s[i] + (dt * 0.125f) * (g_accb[i] + g_k4[i]);
    g_s[i] = v;
    packA_el(pk_s + (size_t)b * 3 * Dd, Dd, j, v);
    if (j >= 1024)
        out_x[((size_t)b * Tt + t + 1) * Xs + (j - 1024)] = v;
}

// ---------------- host ----------------
static inline void gemm(const __nv_bfloat16* A, int lda, int segA,
                        const __nv_bfloat16* B, int ldb, int segB,
                        const float* bias, void* C, int ldc,
                        int M, int N, int K, int mode)
{
    dim3 grid(N / 128, M / 64);
    gemm_bf16<<<grid, 256>>>(A, lda, segA, B, ldb, segB, bias, C, ldc, K, mode);
}

extern "C" void kernel_launch(void* const* d_in, const int* in_sizes, int n_in,
                              void* d_out, int out_size)
{
    const float* x    = (const float*)d_in[0];
    const float* y    = (const float*)d_in[1];
    const float* ts   = (const float*)d_in[2];
    const float* Wiha = (const float*)d_in[3];
    const float* Whha = (const float*)d_in[4];
    const float* biha = (const float*)d_in[5];
    const float* bhha = (const float*)d_in[6];
    const float* Wihx = (const float*)d_in[7];
    const float* Whhx = (const float*)d_in[8];
    const float* bihx = (const float*)d_in[9];
    const float* bhhx = (const float*)d_in[10];
    const float* W1   = (const float*)d_in[11];
    const float* b1   = (const float*)d_in[12];
    const float* W2   = (const float*)d_in[13];
    const float* b2   = (const float*)d_in[14];

    float* out_x  = (float*)d_out;
    float* out_za = out_x + (size_t)Bb * Tt * Xs;

    __nv_bfloat16 *p_s, *p_cat, *p_h, *p_iha, *p_hha, *p_ihx, *p_hhx, *p_w1, *p_w2;
    float *pgia, *pgha, *pgix, *pghx, *pk1, *pk2, *pk3, *pk4;
    cudaGetSymbolAddress((void**)&p_s,   pk_s);
    cudaGetSymbolAddress((void**)&p_cat, pk_cat);
    cudaGetSymbolAddress((void**)&p_h,   pk_h);
    cudaGetSymbolAddress((void**)&p_iha, pw_iha);
    cudaGetSymbolAddress((void**)&p_hha, pw_hha);
    cudaGetSymbolAddress((void**)&p_ihx, pw_ihx);
    cudaGetSymbolAddress((void**)&p_hhx, pw_hhx);
    cudaGetSymbolAddress((void**)&p_w1,  pw_1);
    cudaGetSymbolAddress((void**)&p_w2,  pw_2);
    cudaGetSymbolAddress((void**)&pgia,  g_gia);
    cudaGetSymbolAddress((void**)&pgha,  g_gha);
    cudaGetSymbolAddress((void**)&pgix,  g_gix);
    cudaGetSymbolAddress((void**)&pghx,  g_ghx);
    cudaGetSymbolAddress((void**)&pk1,   g_k1);
    cudaGetSymbolAddress((void**)&pk2,   g_k2);
    cudaGetSymbolAddress((void**)&pk3,   g_k3);
    cudaGetSymbolAddress((void**)&pk4,   g_k4);
    float* ph;
    cudaGetSymbolAddress((void**)&ph, g_k1);  // unused alias

    // weight packing (once per launch; inside graph, deterministic)
    packW_k<<<(G3 * 256 + 255) / 256, 256>>>(Wiha, p_iha, G3, 256);
    packW_k<<<(G3 * 512 + 255) / 256, 256>>>(Whha, p_hha, G3, 512);
    packW_k<<<(G3 * 128 + 255) / 256, 256>>>(Wihx, p_ihx, G3, 128);
    packW_k<<<(G3 * 512 + 255) / 256, 256>>>(Whhx, p_hhx, G3, 512);
    packW_k<<<(Dd * Dd + 255) / 256, 256>>>(W1, p_w1, Dd, Dd);
    packW_k<<<(Dd * Dd + 255) / 256, 256>>>(W2, p_w2, Dd, Dd);

    const int nBD = Bb * Dd, blkBD = (nBD + 255) / 256;
    const int nBH = Bb * XHd, blkBH = (nBH + 255) / 256;

    init_k<<<blkBD, 256>>>(x, out_x, out_za);

    for (int t = 0; t < NSTEP; t++) {
        catmask_k<<<Bb, 128>>>(y, t);
        // GRU gate GEMMs (read packed pre-GRU state / cat)
        gemm(p_cat,        768, 256,  p_iha, 768,  256, biha, pgia, G3, Bb, G3, 256, 0);
        gemm(p_s + XHd,   3456, Dd,   p_hha, 1536, 512, bhha, pgha, G3, Bb, G3, 512, 0);
        gemm(p_s + 1024,  3456, Dd,   p_ihx, 384,  128, bihx, pgix, G3, Bb, G3, 128, 0);
        gemm(p_s,         3456, Dd,   p_hhx, 1536, 512, bhhx, pghx, G3, Bb, G3, 512, 0);
        gru_a_k<<<blkBH, 256>>>(out_za, t);
        gru_x_k<<<blkBH, 256>>>();

        // RK4 (3/8): k1
        gemm(p_s, 3456, Dd, p_w1, 3456, Dd, b1, p_h, 0, Bb, Dd, Dd, 1);
        gemm(p_h, 3456, Dd, p_w2, 3456, Dd, b2, pk1, Dd, Bb, Dd, Dd, 0);
        rk_c1<<<blkBD, 256>>>(ts, t);
        // k2
        gemm(p_s, 3456, Dd, p_w1, 3456, Dd, b1, p_h, 0, Bb, Dd, Dd, 1);
        gemm(p_h, 3456, Dd, p_w2, 3456, Dd, b2, pk2, Dd, Bb, Dd, Dd, 0);
        rk_c2<<<blkBD, 256>>>(ts, t);
        // k3
        gemm(p_s, 3456, Dd, p_w1, 3456, Dd, b1, p_h, 0, Bb, Dd, Dd, 1);
        gemm(p_h, 3456, Dd, p_w2, 3456, Dd, b2, pk3, Dd, Bb, Dd, Dd, 0);
        rk_c3<<<blkBD, 256>>>(ts, t);
        // k4
        gemm(p_s, 3456, Dd, p_w1, 3456, Dd, b1, p_h, 0, Bb, Dd, Dd, 1);
        gemm(p_h, 3456, Dd, p_w2, 3456, Dd, b2, pk4, Dd, Bb, Dd, Dd, 0);
        rk_c4<<<blkBD, 256>>>(ts, out_x, t);
    }
}

// round 6
// speedup vs baseline: 1.8595x; 1.5981x over previous
#include <cuda_runtime.h>
#include <cuda_bf16.h>
#include <math.h>
#include <stdint.h>

#define Bb   1024
#define Tt   32
#define Xs   128
#define XHd  512
#define AHd  512
#define Dd   1152
#define G3   1536
#define NSTEP 31

// ---------------- fp32 scratch ----------------
__device__ float g_s   [Bb * Dd];
__device__ float g_mask[Bb];
__device__ float g_gia [Bb * G3];
__device__ float g_gha [Bb * G3];
__device__ float g_gix [Bb * G3];
__device__ float g_ghx [Bb * G3];
__device__ float g_k1  [Bb * Dd];
__device__ float g_k2  [Bb * Dd];
__device__ float g_k3  [Bb * Dd];
__device__ float g_k4  [Bb * Dd];
__device__ float g_accb[Bb * Dd];

// ---------------- packed bf16 (A-side [hi|hi|lo], B-side [hi|lo|hi]) -----
__device__ __nv_bfloat16 pk_s  [Bb * 3 * Dd];
__device__ __nv_bfloat16 pk_cat[Bb * 3 * 256];
__device__ __nv_bfloat16 pk_h  [Bb * 3 * Dd];
__device__ __nv_bfloat16 pw_iha[G3 * 3 * 256];
__device__ __nv_bfloat16 pw_hha[G3 * 3 * 512];
__device__ __nv_bfloat16 pw_ihx[G3 * 3 * 128];
__device__ __nv_bfloat16 pw_hhx[G3 * 3 * 512];
__device__ __nv_bfloat16 pw_1  [Dd * 3 * Dd];
__device__ __nv_bfloat16 pw_2  [Dd * 3 * Dd];

__device__ __forceinline__ float sigm(float x) { return 1.0f / (1.0f + expf(-x)); }
__device__ __forceinline__ float splus(float x) { return fmaxf(x, 0.f) + log1pf(expf(-fabsf(x))); }

// A-side pack: [hi | hi | lo]
__device__ __forceinline__ void packA_el(__nv_bfloat16* rowbase, int K, int k, float v)
{
    __nv_bfloat16 hi = __float2bfloat16(v);
    __nv_bfloat16 lo = __float2bfloat16(v - __bfloat162float(hi));
    rowbase[k] = hi; rowbase[K + k] = hi; rowbase[2 * K + k] = lo;
}

__device__ __forceinline__ void cpa16(uint32_t sa, const void* g)
{
    asm volatile("cp.async.cg.shared.global [%0], [%1], 16;\n" :: "r"(sa), "l"(g));
}

// ---------------- bf16 split-GEMM: C[M,N] = epi(A'[M,3K] @ B'[N,3K]^T + bias) ----
// BM=64, BN=128, BK=32, 256 threads, warps 2x4, warp tile 32x32 via m16n8k16.
// 4-stage cp.async ring, one __syncthreads per K-tile (issue-after-sync; the
// stage overwritten at iter i is (i-1)&3, whose reads completed before the
// barrier at the top of iter i).
// Segment addressing: col(k') = seg*segX + (k' mod K), seg = k'/K.
// mode 0: C fp32, +bias. mode 1: softplus(.+bias) -> packed bf16 [hi|hi|lo].
#define SSTR 15360
#define SMEM_SZ (4 * SSTR)

__global__ void __launch_bounds__(256) gemm_bf16(
    const __nv_bfloat16* __restrict__ A, int lda, int segA,
    const __nv_bfloat16* __restrict__ B, int ldb, int segB,
    const float* __restrict__ bias,
    void* __restrict__ Cv, int ldc, int K, int mode)
{
    extern __shared__ __align__(16) char smraw[];
    const uint32_t su = (uint32_t)__cvta_generic_to_shared(smraw);

    const int tid = threadIdx.x, lane = tid & 31, wid = tid >> 5;
    const int wm = wid >> 2, wn = wid & 3;
    const int bm = blockIdx.y, bn = blockIdx.x;

    const int arow = tid >> 2, ac8 = (tid & 3) * 8;
    const __nv_bfloat16* Ag  = A + (size_t)(bm * 64 + arow) * lda;
    const __nv_bfloat16* Bg0 = B + (size_t)(bn * 128 + arow) * ldb;
    const __nv_bfloat16* Bg1 = B + (size_t)(bn * 128 + 64 + arow) * ldb;

    const int nk = 3 * K / 32;

    float acc[2][4][4];
#pragma unroll
    for (int i = 0; i < 2; i++)
#pragma unroll
        for (int j = 0; j < 4; j++)
#pragma unroll
            for (int q = 0; q < 4; q++) acc[i][j][q] = 0.f;

#define ISSUE(I)                                                               \
    {                                                                          \
        int kk = (I) * 32;                                                     \
        int seg = (kk >= K) ? ((kk >= 2 * K) ? 2 : 1) : 0;                     \
        int w = kk - seg * K;                                                  \
        int acl = seg * segA + w;                                              \
        int bcl = seg * segB + w;                                              \
        uint32_t sb = su + ((I) & 3) * SSTR;                                   \
        cpa16(sb + arow * 80 + ac8 * 2,               Ag  + acl + ac8);        \
        cpa16(sb + 5120 + arow * 80 + ac8 * 2,        Bg0 + bcl + ac8);        \
        cpa16(sb + 5120 + (64 + arow) * 80 + ac8 * 2, Bg1 + bcl + ac8);        \
        asm volatile("cp.async.commit_group;\n" ::);                           \
    }

    ISSUE(0) ISSUE(1) ISSUE(2)

    for (int i = 0; i < nk; i++) {
        const int st = i & 3;
        const int rem = nk - 1 - i;
        if (rem >= 2)      asm volatile("cp.async.wait_group 2;\n" ::);
        else if (rem == 1) asm volatile("cp.async.wait_group 1;\n" ::);
        else               asm volatile("cp.async.wait_group 0;\n" ::);
        __syncthreads();
        if (i + 3 < nk) ISSUE(i + 3)

        const uint32_t sa_base = su + st * SSTR;
        const uint32_t sb_base = sa_base + 5120;
#pragma unroll
        for (int ks = 0; ks < 2; ks++) {
            const int k0 = ks * 16;
            uint32_t a[2][4], b[4][2];
#pragma unroll
            for (int mi = 0; mi < 2; mi++) {
                uint32_t sa = sa_base + (wm * 32 + mi * 16 + (lane & 15)) * 80
                            + (k0 + (lane >> 4) * 8) * 2;
                asm volatile("ldmatrix.sync.aligned.m8n8.x4.shared.b16 {%0,%1,%2,%3}, [%4];"
                             : "=r"(a[mi][0]), "=r"(a[mi][1]), "=r"(a[mi][2]), "=r"(a[mi][3])
                             : "r"(sa));
            }
#pragma unroll
            for (int ni = 0; ni < 4; ni++) {
                uint32_t sb = sb_base + (wn * 32 + ni * 8 + (lane & 7)) * 80
                            + (k0 + ((lane >> 3) & 1) * 8) * 2;
                asm volatile("ldmatrix.sync.aligned.m8n8.x2.shared.b16 {%0,%1}, [%2];"
                             : "=r"(b[ni][0]), "=r"(b[ni][1])
                             : "r"(sb));
            }
#pragma unroll
            for (int mi = 0; mi < 2; mi++)
#pragma unroll
                for (int ni = 0; ni < 4; ni++) {
                    asm volatile(
                        "mma.sync.aligned.m16n8k16.row.col.f32.bf16.bf16.f32 "
                        "{%0,%1,%2,%3}, {%4,%5,%6,%7}, {%8,%9}, {%0,%1,%2,%3};"
                        : "+f"(acc[mi][ni][0]), "+f"(acc[mi][ni][1]),
                          "+f"(acc[mi][ni][2]), "+f"(acc[mi][ni][3])
                        : "r"(a[mi][0]), "r"(a[mi][1]), "r"(a[mi][2]), "r"(a[mi][3]),
                          "r"(b[ni][0]), "r"(b[ni][1]));
                }
        }
    }
#undef ISSUE

    const int rbase = bm * 64 + wm * 32;
    const int cbase = bn * 128 + wn * 32;

    if (mode == 0) {
        float* C = (float*)Cv;
#pragma unroll
        for (int mi = 0; mi < 2; mi++)
#pragma unroll
            for (int ni = 0; ni < 4; ni++) {
                int r0 = rbase + mi * 16 + (lane >> 2);
                int c0 = cbase + ni * 8 + (lane & 3) * 2;
                float b0 = bias[c0], b1 = bias[c0 + 1];
                float2 o0 = make_float2(acc[mi][ni][0] + b0, acc[mi][ni][1] + b1);
                float2 o1 = make_float2(acc[mi][ni][2] + b0, acc[mi][ni][3] + b1);
                *(float2*)(C + (size_t)r0 * ldc + c0) = o0;
                *(float2*)(C + (size_t)(r0 + 8) * ldc + c0) = o1;
            }
    } else {
        __nv_bfloat16* C = (__nv_bfloat16*)Cv;  // packed, row stride 3K
#pragma unroll
        for (int mi = 0; mi < 2; mi++)
#pragma unroll
            for (int ni = 0; ni < 4; ni++) {
                int r0 = rbase + mi * 16 + (lane >> 2);
                int c0 = cbase + ni * 8 + (lane & 3) * 2;
                float b0 = bias[c0], b1 = bias[c0 + 1];
#pragma unroll
                for (int h = 0; h < 2; h++) {
                    float v0 = splus(acc[mi][ni][2 * h + 0] + b0);
                    float v1 = splus(acc[mi][ni][2 * h + 1] + b1);
                    __nv_bfloat16 h0 = __float2bfloat16(v0), h1 = __float2bfloat16(v1);
                    __nv_bfloat16 l0 = __float2bfloat16(v0 - __bfloat162float(h0));
                    __nv_bfloat16 l1 = __float2bfloat16(v1 - __bfloat162float(h1));
                    __nv_bfloat162 hh; hh.x = h0; hh.y = h1;
                    __nv_bfloat162 ll; ll.x = l0; ll.y = l1;
                    __nv_bfloat16* base = C + (size_t)(r0 + 8 * h) * (3 * K) + c0;
                    *(__nv_bfloat162*)(base)         = hh;
                    *(__nv_bfloat162*)(base + K)     = hh;
                    *(__nv_bfloat162*)(base + 2 * K) = ll;
                }
            }
    }
}

// ---------------- weight pack (B-side: [hi | lo | hi]) ----------------
__global__ void packW_k(const float* __restrict__ in, __nv_bfloat16* __restrict__ out,
                        int N, int K)
{
    int idx = blockIdx.x * blockDim.x + threadIdx.x;
    if (idx >= N * K) return;
    int n = idx / K, k = idx % K;
    float v = in[(size_t)n * K + k];
    __nv_bfloat16 hi = __float2bfloat16(v);
    __nv_bfloat16 lo = __float2bfloat16(v - __bfloat162float(hi));
    __nv_bfloat16* o = out + (size_t)n * 3 * K;
    o[k] = hi; o[K + k] = lo; o[2 * K + k] = hi;
}

// ---------------- elementwise (fused state packing) ----------------
__global__ void init_k(const float* __restrict__ x, float* __restrict__ out_x,
                       float* __restrict__ out_za)
{
    int idx = blockIdx.x * blockDim.x + threadIdx.x;
    if (idx >= Bb * Dd) return;
    int b = idx / Dd, j = idx % Dd;
    float v;
    if (j < 1024) {
        v = 0.0f;
        if (j < AHd) out_za[((size_t)b * Tt) * AHd + j] = 0.0f;
    } else {
        v = x[((size_t)b * Tt) * Xs + (j - 1024)];
        out_x[((size_t)b * Tt) * Xs + (j - 1024)] = v;
    }
    g_s[idx] = v;
    packA_el(pk_s + (size_t)b * 3 * Dd, Dd, j, v);
}

__global__ void catmask_k(const float* __restrict__ y, int t)
{
    int b = blockIdx.x;
    int c = threadIdx.x;  // 128
    float yv = y[((size_t)b * Tt + t) * 128 + c];
    float xv = g_s[b * Dd + 1024 + c];
    __nv_bfloat16* rb = pk_cat + (size_t)b * 768;
    packA_el(rb, 256, c, xv);
    packA_el(rb, 256, 128 + c, yv);
    __shared__ float red[128];
    red[c] = yv;
    __syncthreads();
    for (int o = 64; o > 0; o >>= 1) {
        if (c < o) red[c] += red[c + o];
        __syncthreads();
    }
    if (c == 0) g_mask[b] = (red[0] != 0.0f) ? 1.0f : 0.0f;
}

__global__ void gru_a_k(float* __restrict__ out_za, int t)
{
    int idx = blockIdx.x * blockDim.x + threadIdx.x;
    if (idx >= Bb * AHd) return;
    int b = idx / AHd, j = idx % AHd;
    const float* gi = g_gia + (size_t)b * G3;
    const float* gh = g_gha + (size_t)b * G3;
    float r = sigm(gi[j] + gh[j]);
    float z = sigm(gi[AHd + j] + gh[AHd + j]);
    float n = tanhf(gi[2 * AHd + j] + r * gh[2 * AHd + j]);
    float h = g_s[b * Dd + XHd + j];
    float hn = (1.0f - z) * n + z * h;
    float v = (g_mask[b] != 0.0f) ? hn : h;
    g_s[b * Dd + XHd + j] = v;
    packA_el(pk_s + (size_t)b * 3 * Dd, Dd, XHd + j, v);
    out_za[((size_t)b * Tt + t + 1) * AHd + j] = v;
}

__global__ void gru_x_k()
{
    int idx = blockIdx.x * blockDim.x + threadIdx.x;
    if (idx >= Bb * XHd) return;
    int b = idx / XHd, j = idx % XHd;
    const float* gi = g_gix + (size_t)b * G3;
    const float* gh = g_ghx + (size_t)b * G3;
    float r = sigm(gi[j] + gh[j]);
    float z = sigm(gi[XHd + j] + gh[XHd + j]);
    float n = tanhf(gi[2 * XHd + j] + r * gh[2 * XHd + j]);
    float h = g_s[b * Dd + j];
    float v = (1.0f - z) * n + z * h;
    g_s[b * Dd + j] = v;
    packA_el(pk_s + (size_t)b * 3 * Dd, Dd, j, v);
}

__global__ void rk_c1(const float* __restrict__ ts, int t)
{
    int i = blockIdx.x * blockDim.x + threadIdx.x;
    if (i >= Bb * Dd) return;
    float dt = ts[t + 1] - ts[t];
    int b = i / Dd, j = i % Dd;
    float v = g_s[i] + (dt * (1.0f / 3.0f)) * g_k1[i];
    packA_el(pk_s + (size_t)b * 3 * Dd, Dd, j, v);
}
__global__ void rk_c2(const float* __restrict__ ts, int t)
{
    int i = blockIdx.x * blockDim.x + threadIdx.x;
    if (i >= Bb * Dd) return;
    float dt = ts[t + 1] - ts[t];
    int b = i / Dd, j = i % Dd;
    float k1 = g_k1[i], k2 = g_k2[i];
    float v = g_s[i] + dt * (k2 - k1 * (1.0f / 3.0f));
    g_accb[i] = k1 + 3.0f * k2;
    packA_el(pk_s + (size_t)b * 3 * Dd, Dd, j, v);
}
__global__ void rk_c3(const float* __restrict__ ts, int t)
{
    int i = blockIdx.x * blockDim.x + threadIdx.x;
    if (i >= Bb * Dd) return;
    float dt = ts[t + 1] - ts[t];
    int b = i / Dd, j = i % Dd;
    float k1 = g_k1[i], k2 = g_k2[i], k3 = g_k3[i];
    float v = g_s[i] + dt * (k1 - k2 + k3);
    g_accb[i] = g_accb[i] + 3.0f * k3;
    packA_el(pk_s + (size_t)b * 3 * Dd, Dd, j, v);
}
__global__ void rk_c4(const float* __restrict__ ts, float* __restrict__ out_x, int t)
{
    int i = blockIdx.x * blockDim.x + threadIdx.x;
    if (i >= Bb * Dd) return;
    float dt = ts[t + 1] - ts[t];
    int b = i / Dd, j = i % Dd;
    float v = g_s[i] + (dt * 0.125f) * (g_accb[i] + g_k4[i]);
    g_s[i] = v;
    packA_el(pk_s + (size_t)b * 3 * Dd, Dd, j, v);
    if (j >= 1024)
        out_x[((size_t)b * Tt + t + 1) * Xs + (j - 1024)] = v;
}

// ---------------- host ----------------
static inline void gemm(const __nv_bfloat16* A, int lda, int segA,
                        const __nv_bfloat16* B, int ldb, int segB,
                        const float* bias, void* C, int ldc,
                        int M, int N, int K, int mode)
{
    dim3 grid(N / 128, M / 64);
    gemm_bf16<<<grid, 256, SMEM_SZ>>>(A, lda, segA, B, ldb, segB, bias, C, ldc, K, mode);
}

extern "C" void kernel_launch(void* const* d_in, const int* in_sizes, int n_in,
                              void* d_out, int out_size)
{
    const float* x    = (const float*)d_in[0];
    const float* y    = (const float*)d_in[1];
    const float* ts   = (const float*)d_in[2];
    const float* Wiha = (const float*)d_in[3];
    const float* Whha = (const float*)d_in[4];
    const float* biha = (const float*)d_in[5];
    const float* bhha = (const float*)d_in[6];
    const float* Wihx = (const float*)d_in[7];
    const float* Whhx = (const float*)d_in[8];
    const float* bihx = (const float*)d_in[9];
    const float* bhhx = (const float*)d_in[10];
    const float* W1   = (const float*)d_in[11];
    const float* b1   = (const float*)d_in[12];
    const float* W2   = (const float*)d_in[13];
    const float* b2   = (const float*)d_in[14];

    float* out_x  = (float*)d_out;
    float* out_za = out_x + (size_t)Bb * Tt * Xs;

    cudaFuncSetAttribute(gemm_bf16, cudaFuncAttributeMaxDynamicSharedMemorySize, SMEM_SZ);

    __nv_bfloat16 *p_s, *p_cat, *p_h, *p_iha, *p_hha, *p_ihx, *p_hhx, *p_w1, *p_w2;
    float *pgia, *pgha, *pgix, *pghx, *pk1, *pk2, *pk3, *pk4;
    cudaGetSymbolAddress((void**)&p_s,   pk_s);
    cudaGetSymbolAddress((void**)&p_cat, pk_cat);
    cudaGetSymbolAddress((void**)&p_h,   pk_h);
    cudaGetSymbolAddress((void**)&p_iha, pw_iha);
    cudaGetSymbolAddress((void**)&p_hha, pw_hha);
    cudaGetSymbolAddress((void**)&p_ihx, pw_ihx);
    cudaGetSymbolAddress((void**)&p_hhx, pw_hhx);
    cudaGetSymbolAddress((void**)&p_w1,  pw_1);
    cudaGetSymbolAddress((void**)&p_w2,  pw_2);
    cudaGetSymbolAddress((void**)&pgia,  g_gia);
    cudaGetSymbolAddress((void**)&pgha,  g_gha);
    cudaGetSymbolAddress((void**)&pgix,  g_gix);
    cudaGetSymbolAddress((void**)&pghx,  g_ghx);
    cudaGetSymbolAddress((void**)&pk1,   g_k1);
    cudaGetSymbolAddress((void**)&pk2,   g_k2);
    cudaGetSymbolAddress((void**)&pk3,   g_k3);
    cudaGetSymbolAddress((void**)&pk4,   g_k4);

    packW_k<<<(G3 * 256 + 255) / 256, 256>>>(Wiha, p_iha, G3, 256);
    packW_k<<<(G3 * 512 + 255) / 256, 256>>>(Whha, p_hha, G3, 512);
    packW_k<<<(G3 * 128 + 255) / 256, 256>>>(Wihx, p_ihx, G3, 128);
    packW_k<<<(G3 * 512 + 255) / 256, 256>>>(Whhx, p_hhx, G3, 512);
    packW_k<<<(Dd * Dd + 255) / 256, 256>>>(W1, p_w1, Dd, Dd);
    packW_k<<<(Dd * Dd + 255) / 256, 256>>>(W2, p_w2, Dd, Dd);

    const int nBD = Bb * Dd, blkBD = (nBD + 255) / 256;
    const int nBH = Bb * XHd, blkBH = (nBH + 255) / 256;

    init_k<<<blkBD, 256>>>(x, out_x, out_za);

    for (int t = 0; t < NSTEP; t++) {
        catmask_k<<<Bb, 128>>>(y, t);
        gemm(p_cat,        768, 256,  p_iha, 768,  256, biha, pgia, G3, Bb, G3, 256, 0);
        gemm(p_s + XHd,   3456, Dd,   p_hha, 1536, 512, bhha, pgha, G3, Bb, G3, 512, 0);
        gemm(p_s + 1024,  3456, Dd,   p_ihx, 384,  128, bihx, pgix, G3, Bb, G3, 128, 0);
        gemm(p_s,         3456, Dd,   p_hhx, 1536, 512, bhhx, pghx, G3, Bb, G3, 512, 0);
        gru_a_k<<<blkBH, 256>>>(out_za, t);
        gru_x_k<<<blkBH, 256>>>();

        gemm(p_s, 3456, Dd, p_w1, 3456, Dd, b1, p_h, 0, Bb, Dd, Dd, 1);
        gemm(p_h, 3456, Dd, p_w2, 3456, Dd, b2, pk1, Dd, Bb, Dd, Dd, 0);
        rk_c1<<<blkBD, 256>>>(ts, t);
        gemm(p_s, 3456, Dd, p_w1, 3456, Dd, b1, p_h, 0, Bb, Dd, Dd, 1);
        gemm(p_h, 3456, Dd, p_w2, 3456, Dd, b2, pk2, Dd, Bb, Dd, Dd, 0);
        rk_c2<<<blkBD, 256>>>(ts, t);
        gemm(p_s, 3456, Dd, p_w1, 3456, Dd, b1, p_h, 0, Bb, Dd, Dd, 1);
        gemm(p_h, 3456, Dd, p_w2, 3456, Dd, b2, pk3, Dd, Bb, Dd, Dd, 0);
        rk_c3<<<blkBD, 256>>>(ts, t);
        gemm(p_s, 3456, Dd, p_w1, 3456, Dd, b1, p_h, 0, Bb, Dd, Dd, 1);
        gemm(p_h, 3456, Dd, p_w2, 3456, Dd, b2, pk4, Dd, Bb, Dd, Dd, 0);
        rk_c4<<<blkBD, 256>>>(ts, out_x, t);
    }
}

// round 7
// speedup vs baseline: 2.0302x; 1.0918x over previous
#include <cuda_runtime.h>
#include <cuda_bf16.h>
#include <math.h>
#include <stdint.h>

#define Bb   1024
#define Tt   32
#define Xs   128
#define XHd  512
#define AHd  512
#define Dd   1152
#define G3   1536
#define NSTEP 31

typedef __nv_bfloat16 bf16;
typedef __nv_bfloat162 bf162;

// ---------------- fp32 scratch ----------------
__device__ float g_s   [Bb * Dd];
__device__ float g_mask[Bb];
__device__ float g_gia [Bb * G3];
__device__ float g_gha [Bb * G3];
__device__ float g_gix [Bb * G3];
__device__ float g_ghx [Bb * G3];
__device__ float g_k1  [Bb * Dd];
__device__ float g_k2  [Bb * Dd];
__device__ float g_k3  [Bb * Dd];
__device__ float g_k4  [Bb * Dd];
__device__ float g_accb[Bb * Dd];

// ---------------- packed bf16 (A-side [hi|hi|lo], B-side [hi|lo|hi]) -----
__device__ bf16 pk_s  [Bb * 3 * Dd];
__device__ bf16 pk_cat[Bb * 3 * 256];
__device__ bf16 pk_h  [Bb * 3 * Dd];
__device__ bf16 pw_iha[G3 * 3 * 256];
__device__ bf16 pw_hha[G3 * 3 * 512];
__device__ bf16 pw_ihx[G3 * 3 * 128];
__device__ bf16 pw_hhx[G3 * 3 * 512];
__device__ bf16 pw_1  [Dd * 3 * Dd];
__device__ bf16 pw_2  [Dd * 3 * Dd];

__device__ __forceinline__ float sigm(float x) { return 1.0f / (1.0f + expf(-x)); }
__device__ __forceinline__ float splus(float x) { return fmaxf(x, 0.f) + log1pf(expf(-fabsf(x))); }

// A-side pack: [hi | hi | lo]
__device__ __forceinline__ void packA_el(bf16* rowbase, int K, int k, float v)
{
    bf16 hi = __float2bfloat16(v);
    bf16 lo = __float2bfloat16(v - __bfloat162float(hi));
    rowbase[k] = hi; rowbase[K + k] = hi; rowbase[2 * K + k] = lo;
}

__device__ __forceinline__ void cpa16(uint32_t sa, const void* g)
{
    asm volatile("cp.async.cg.shared.global [%0], [%1], 16;\n" :: "r"(sa), "l"(g));
}

// ---------------- batched bf16 split-GEMM ----------------
// Per z-slice: C[M,N] = epi(A'[M,3K] @ B'[N,3K]^T + bias)
// BM=64, BN=128, BK=32, 256 threads, warps 2x4, warp tile 32x32, 4 stages,
// one __syncthreads per K-tile. Segment addressing: col = seg*seg{A,B} + (k' mod K).
// mode 0: C fp32 + bias (ldc). mode 1: softplus -> packed bf16 [hi|hi|lo], stride 3K.
struct Cfg {
    const bf16 *A, *B;
    const float *bias;
    void *Cv;
    int lda, segA, ldb, segB, ldc, K, mode;
};
struct Cfg4 { Cfg c[4]; };

#define SSTR 15360
#define SMEM_SZ (4 * SSTR)

__global__ void __launch_bounds__(256) gemm_bf16(Cfg4 P)
{
    const Cfg cg = P.c[blockIdx.z];
    const bf16* __restrict__ A = cg.A;
    const bf16* __restrict__ B = cg.B;
    const int lda = cg.lda, segA = cg.segA, ldb = cg.ldb, segB = cg.segB;
    const int K = cg.K;
    const int nk = 3 * K / 32;

    extern __shared__ __align__(16) char smraw[];
    const uint32_t su = (uint32_t)__cvta_generic_to_shared(smraw);

    const int tid = threadIdx.x, lane = tid & 31, wid = tid >> 5;
    const int wm = wid >> 2, wn = wid & 3;
    const int bm = blockIdx.y, bn = blockIdx.x;

    const int arow = tid >> 2, ac8 = (tid & 3) * 8;
    const bf16* Ag  = A + (size_t)(bm * 64 + arow) * lda;
    const bf16* Bg0 = B + (size_t)(bn * 128 + arow) * ldb;
    const bf16* Bg1 = B + (size_t)(bn * 128 + 64 + arow) * ldb;

    float acc[2][4][4];
#pragma unroll
    for (int i = 0; i < 2; i++)
#pragma unroll
        for (int j = 0; j < 4; j++)
#pragma unroll
            for (int q = 0; q < 4; q++) acc[i][j][q] = 0.f;

#define ISSUE(I)                                                               \
    {                                                                          \
        int kk = (I) * 32;                                                     \
        int seg = (kk >= K) ? ((kk >= 2 * K) ? 2 : 1) : 0;                     \
        int w = kk - seg * K;                                                  \
        int acl = seg * segA + w;                                              \
        int bcl = seg * segB + w;                                              \
        uint32_t sb = su + ((I) & 3) * SSTR;                                   \
        cpa16(sb + arow * 80 + ac8 * 2,               Ag  + acl + ac8);        \
        cpa16(sb + 5120 + arow * 80 + ac8 * 2,        Bg0 + bcl + ac8);        \
        cpa16(sb + 5120 + (64 + arow) * 80 + ac8 * 2, Bg1 + bcl + ac8);        \
        asm volatile("cp.async.commit_group;\n" ::);                           \
    }

    ISSUE(0) ISSUE(1) ISSUE(2)

    for (int i = 0; i < nk; i++) {
        const int st = i & 3;
        const int rem = nk - 1 - i;
        if (rem >= 2)      asm volatile("cp.async.wait_group 2;\n" ::);
        else if (rem == 1) asm volatile("cp.async.wait_group 1;\n" ::);
        else               asm volatile("cp.async.wait_group 0;\n" ::);
        __syncthreads();
        if (i + 3 < nk) ISSUE(i + 3)

        const uint32_t sa_base = su + st * SSTR;
        const uint32_t sb_base = sa_base + 5120;
#pragma unroll
        for (int ks = 0; ks < 2; ks++) {
            const int k0 = ks * 16;
            uint32_t a[2][4], b[4][2];
#pragma unroll
            for (int mi = 0; mi < 2; mi++) {
                uint32_t sa = sa_base + (wm * 32 + mi * 16 + (lane & 15)) * 80
                            + (k0 + (lane >> 4) * 8) * 2;
                asm volatile("ldmatrix.sync.aligned.m8n8.x4.shared.b16 {%0,%1,%2,%3}, [%4];"
                             : "=r"(a[mi][0]), "=r"(a[mi][1]), "=r"(a[mi][2]), "=r"(a[mi][3])
                             : "r"(sa));
            }
            // B: one x4 per ni-pair (same fragments as two x2's)
#pragma unroll
            for (int p = 0; p < 2; p++) {
                uint32_t sb = sb_base
                            + (wn * 32 + (2 * p + ((lane >> 4) & 1)) * 8 + (lane & 7)) * 80
                            + (k0 + ((lane >> 3) & 1) * 8) * 2;
                asm volatile("ldmatrix.sync.aligned.m8n8.x4.shared.b16 {%0,%1,%2,%3}, [%4];"
                             : "=r"(b[2 * p][0]), "=r"(b[2 * p][1]),
                               "=r"(b[2 * p + 1][0]), "=r"(b[2 * p + 1][1])
                             : "r"(sb));
            }
#pragma unroll
            for (int mi = 0; mi < 2; mi++)
#pragma unroll
                for (int ni = 0; ni < 4; ni++) {
                    asm volatile(
                        "mma.sync.aligned.m16n8k16.row.col.f32.bf16.bf16.f32 "
                        "{%0,%1,%2,%3}, {%4,%5,%6,%7}, {%8,%9}, {%0,%1,%2,%3};"
                        : "+f"(acc[mi][ni][0]), "+f"(acc[mi][ni][1]),
                          "+f"(acc[mi][ni][2]), "+f"(acc[mi][ni][3])
                        : "r"(a[mi][0]), "r"(a[mi][1]), "r"(a[mi][2]), "r"(a[mi][3]),
                          "r"(b[ni][0]), "r"(b[ni][1]));
                }
        }
    }
#undef ISSUE

    const int rbase = bm * 64 + wm * 32;
    const int cbase = bn * 128 + wn * 32;
    const float* bias = cg.bias;

    if (cg.mode == 0) {
        float* C = (float*)cg.Cv;
        const int ldc = cg.ldc;
#pragma unroll
        for (int mi = 0; mi < 2; mi++)
#pragma unroll
            for (int ni = 0; ni < 4; ni++) {
                int r0 = rbase + mi * 16 + (lane >> 2);
                int c0 = cbase + ni * 8 + (lane & 3) * 2;
                float b0 = bias[c0], b1 = bias[c0 + 1];
                float2 o0 = make_float2(acc[mi][ni][0] + b0, acc[mi][ni][1] + b1);
                float2 o1 = make_float2(acc[mi][ni][2] + b0, acc[mi][ni][3] + b1);
                *(float2*)(C + (size_t)r0 * ldc + c0) = o0;
                *(float2*)(C + (size_t)(r0 + 8) * ldc + c0) = o1;
            }
    } else {
        bf16* C = (bf16*)cg.Cv;  // packed, row stride 3K
#pragma unroll
        for (int mi = 0; mi < 2; mi++)
#pragma unroll
            for (int ni = 0; ni < 4; ni++) {
                int r0 = rbase + mi * 16 + (lane >> 2);
                int c0 = cbase + ni * 8 + (lane & 3) * 2;
                float b0 = bias[c0], b1 = bias[c0 + 1];
#pragma unroll
                for (int h = 0; h < 2; h++) {
                    float v0 = splus(acc[mi][ni][2 * h + 0] + b0);
                    float v1 = splus(acc[mi][ni][2 * h + 1] + b1);
                    bf16 h0 = __float2bfloat16(v0), h1 = __float2bfloat16(v1);
                    bf16 l0 = __float2bfloat16(v0 - __bfloat162float(h0));
                    bf16 l1 = __float2bfloat16(v1 - __bfloat162float(h1));
                    bf162 hh; hh.x = h0; hh.y = h1;
                    bf162 ll; ll.x = l0; ll.y = l1;
                    bf16* base = C + (size_t)(r0 + 8 * h) * (3 * K) + c0;
                    *(bf162*)(base)         = hh;
                    *(bf162*)(base + K)     = hh;
                    *(bf162*)(base + 2 * K) = ll;
                }
            }
    }
}

// ---------------- weight pack (B-side: [hi | lo | hi]) ----------------
__global__ void packW_k(const float* __restrict__ in, bf16* __restrict__ out,
                        int N, int K)
{
    int idx = blockIdx.x * blockDim.x + threadIdx.x;
    if (idx >= N * K) return;
    int n = idx / K, k = idx % K;
    float v = in[(size_t)n * K + k];
    bf16 hi = __float2bfloat16(v);
    bf16 lo = __float2bfloat16(v - __bfloat162float(hi));
    bf16* o = out + (size_t)n * 3 * K;
    o[k] = hi; o[K + k] = lo; o[2 * K + k] = hi;
}

// ---------------- elementwise (fused state packing) ----------------
__global__ void init_k(const float* __restrict__ x, float* __restrict__ out_x,
                       float* __restrict__ out_za)
{
    int idx = blockIdx.x * blockDim.x + threadIdx.x;
    if (idx >= Bb * Dd) return;
    int b = idx / Dd, j = idx % Dd;
    float v;
    if (j < 1024) {
        v = 0.0f;
        if (j < AHd) out_za[((size_t)b * Tt) * AHd + j] = 0.0f;
    } else {
        v = x[((size_t)b * Tt) * Xs + (j - 1024)];
        out_x[((size_t)b * Tt) * Xs + (j - 1024)] = v;
    }
    g_s[idx] = v;
    packA_el(pk_s + (size_t)b * 3 * Dd, Dd, j, v);
}

__global__ void catmask_k(const float* __restrict__ y, int t)
{
    int b = blockIdx.x;
    int c = threadIdx.x;  // 128
    float yv = y[((size_t)b * Tt + t) * 128 + c];
    float xv = g_s[b * Dd + 1024 + c];
    bf16* rb = pk_cat + (size_t)b * 768;
    packA_el(rb, 256, c, xv);
    packA_el(rb, 256, 128 + c, yv);
    __shared__ float red[128];
    red[c] = yv;
    __syncthreads();
    for (int o = 64; o > 0; o >>= 1) {
        if (c < o) red[c] += red[c + o];
        __syncthreads();
    }
    if (c == 0) g_mask[b] = (red[0] != 0.0f) ? 1.0f : 0.0f;
}

// merged GRU (z_x for j<512, z_a for j>=512) — math identical to gru_x_k/gru_a_k
__global__ void gru_k(float* __restrict__ out_za, int t)
{
    int idx = blockIdx.x * blockDim.x + threadIdx.x;
    if (idx >= Bb * 1024) return;
    int b = idx >> 10, j = idx & 1023;
    if (j < XHd) {
        const float* gi = g_gix + (size_t)b * G3;
        const float* gh = g_ghx + (size_t)b * G3;
        float r = sigm(gi[j] + gh[j]);
        float z = sigm(gi[XHd + j] + gh[XHd + j]);
        float n = tanhf(gi[2 * XHd + j] + r * gh[2 * XHd + j]);
        float h = g_s[b * Dd + j];
        float v = (1.0f - z) * n + z * h;
        g_s[b * Dd + j] = v;
        packA_el(pk_s + (size_t)b * 3 * Dd, Dd, j, v);
    } else {
        int ja = j - XHd;
        const float* gi = g_gia + (size_t)b * G3;
        const float* gh = g_gha + (size_t)b * G3;
        float r = sigm(gi[ja] + gh[ja]);
        float z = sigm(gi[AHd + ja] + gh[AHd + ja]);
        float n = tanhf(gi[2 * AHd + ja] + r * gh[2 * AHd + ja]);
        float h = g_s[b * Dd + XHd + ja];
        float hn = (1.0f - z) * n + z * h;
        float v = (g_mask[b] != 0.0f) ? hn : h;
        g_s[b * Dd + XHd + ja] = v;
        packA_el(pk_s + (size_t)b * 3 * Dd, Dd, XHd + ja, v);
        out_za[((size_t)b * Tt + t + 1) * AHd + ja] = v;
    }
}

__global__ void rk_c1(const float* __restrict__ ts, int t)
{
    int i = blockIdx.x * blockDim.x + threadIdx.x;
    if (i >= Bb * Dd) return;
    float dt = ts[t + 1] - ts[t];
    int b = i / Dd, j = i % Dd;
    float v = g_s[i] + (dt * (1.0f / 3.0f)) * g_k1[i];
    packA_el(pk_s + (size_t)b * 3 * Dd, Dd, j, v);
}
__global__ void rk_c2(const float* __restrict__ ts, int t)
{
    int i = blockIdx.x * blockDim.x + threadIdx.x;
    if (i >= Bb * Dd) return;
    float dt = ts[t + 1] - ts[t];
    int b = i / Dd, j = i % Dd;
    float k1 = g_k1[i], k2 = g_k2[i];
    float v = g_s[i] + dt * (k2 - k1 * (1.0f / 3.0f));
    g_accb[i] = k1 + 3.0f * k2;
    packA_el(pk_s + (size_t)b * 3 * Dd, Dd, j, v);
}
__global__ void rk_c3(const float* __restrict__ ts, int t)
{
    int i = blockIdx.x * blockDim.x + threadIdx.x;
    if (i >= Bb * Dd) return;
    float dt = ts[t + 1] - ts[t];
    int b = i / Dd, j = i % Dd;
    float k1 = g_k1[i], k2 = g_k2[i], k3 = g_k3[i];
    float v = g_s[i] + dt * (k1 - k2 + k3);
    g_accb[i] = g_accb[i] + 3.0f * k3;
    packA_el(pk_s + (size_t)b * 3 * Dd, Dd, j, v);
}
__global__ void rk_c4(const float* __restrict__ ts, float* __restrict__ out_x, int t)
{
    int i = blockIdx.x * blockDim.x + threadIdx.x;
    if (i >= Bb * Dd) return;
    float dt = ts[t + 1] - ts[t];
    int b = i / Dd, j = i % Dd;
    float v = g_s[i] + (dt * 0.125f) * (g_accb[i] + g_k4[i]);
    g_s[i] = v;
    packA_el(pk_s + (size_t)b * 3 * Dd, Dd, j, v);
    if (j >= 1024)
        out_x[((size_t)b * Tt + t + 1) * Xs + (j - 1024)] = v;
}

// ---------------- host ----------------
static inline Cfg mkcfg(const bf16* A, int lda, int segA,
                        const bf16* B, int ldb, int segB,
                        const float* bias, void* C, int ldc, int K, int mode)
{
    Cfg c; c.A = A; c.B = B; c.bias = bias; c.Cv = C;
    c.lda = lda; c.segA = segA; c.ldb = ldb; c.segB = segB;
    c.ldc = ldc; c.K = K; c.mode = mode;
    return c;
}

extern "C" void kernel_launch(void* const* d_in, const int* in_sizes, int n_in,
                              void* d_out, int out_size)
{
    const float* x    = (const float*)d_in[0];
    const float* y    = (const float*)d_in[1];
    const float* ts   = (const float*)d_in[2];
    const float* Wiha = (const float*)d_in[3];
    const float* Whha = (const float*)d_in[4];
    const float* biha = (const float*)d_in[5];
    const float* bhha = (const float*)d_in[6];
    const float* Wihx = (const float*)d_in[7];
    const float* Whhx = (const float*)d_in[8];
    const float* bihx = (const float*)d_in[9];
    const float* bhhx = (const float*)d_in[10];
    const float* W1   = (const float*)d_in[11];
    const float* b1   = (const float*)d_in[12];
    const float* W2   = (const float*)d_in[13];
    const float* b2   = (const float*)d_in[14];

    float* out_x  = (float*)d_out;
    float* out_za = out_x + (size_t)Bb * Tt * Xs;

    cudaFuncSetAttribute(gemm_bf16, cudaFuncAttributeMaxDynamicSharedMemorySize, SMEM_SZ);

    bf16 *p_s, *p_cat, *p_h, *p_iha, *p_hha, *p_ihx, *p_hhx, *p_w1, *p_w2;
    float *pgia, *pgha, *pgix, *pghx, *pk1, *pk2, *pk3, *pk4;
    cudaGetSymbolAddress((void**)&p_s,   pk_s);
    cudaGetSymbolAddress((void**)&p_cat, pk_cat);
    cudaGetSymbolAddress((void**)&p_h,   pk_h);
    cudaGetSymbolAddress((void**)&p_iha, pw_iha);
    cudaGetSymbolAddress((void**)&p_hha, pw_hha);
    cudaGetSymbolAddress((void**)&p_ihx, pw_ihx);
    cudaGetSymbolAddress((void**)&p_hhx, pw_hhx);
    cudaGetSymbolAddress((void**)&p_w1,  pw_1);
    cudaGetSymbolAddress((void**)&p_w2,  pw_2);
    cudaGetSymbolAddress((void**)&pgia,  g_gia);
    cudaGetSymbolAddress((void**)&pgha,  g_gha);
    cudaGetSymbolAddress((void**)&pgix,  g_gix);
    cudaGetSymbolAddress((void**)&pghx,  g_ghx);
    cudaGetSymbolAddress((void**)&pk1,   g_k1);
    cudaGetSymbolAddress((void**)&pk2,   g_k2);
    cudaGetSymbolAddress((void**)&pk3,   g_k3);
    cudaGetSymbolAddress((void**)&pk4,   g_k4);

    packW_k<<<(G3 * 256 + 255) / 256, 256>>>(Wiha, p_iha, G3, 256);
    packW_k<<<(G3 * 512 + 255) / 256, 256>>>(Whha, p_hha, G3, 512);
    packW_k<<<(G3 * 128 + 255) / 256, 256>>>(Wihx, p_ihx, G3, 128);
    packW_k<<<(G3 * 512 + 255) / 256, 256>>>(Whhx, p_hhx, G3, 512);
    packW_k<<<(Dd * Dd + 255) / 256, 256>>>(W1, p_w1, Dd, Dd);
    packW_k<<<(Dd * Dd + 255) / 256, 256>>>(W2, p_w2, Dd, Dd);

    const int blkBD = (Bb * Dd + 255) / 256;
    const int blkG  = (Bb * 1024 + 255) / 256;

    init_k<<<blkBD, 256>>>(x, out_x, out_za);

    const dim3 gridGate(G3 / 128, Bb / 64, 4);
    const dim3 gridD(Dd / 128, Bb / 64, 1);

    for (int t = 0; t < NSTEP; t++) {
        catmask_k<<<Bb, 128>>>(y, t);

        Cfg4 G;
        G.c[0] = mkcfg(p_cat,        768, 256,  p_iha, 768,  256, biha, pgia, G3, 256, 0);
        G.c[1] = mkcfg(p_s + XHd,   3456, 1152, p_hha, 1536, 512, bhha, pgha, G3, 512, 0);
        G.c[2] = mkcfg(p_s + 1024,  3456, 1152, p_ihx, 384,  128, bihx, pgix, G3, 128, 0);
        G.c[3] = mkcfg(p_s,         3456, 1152, p_hhx, 1536, 512, bhhx, pghx, G3, 512, 0);
        gemm_bf16<<<gridGate, 256, SMEM_SZ>>>(G);

        gru_k<<<blkG, 256>>>(out_za, t);

        float* kouts[4] = {pk1, pk2, pk3, pk4};
        for (int q = 0; q < 4; q++) {
            Cfg4 S1;
            S1.c[0] = mkcfg(p_s, 3456, 1152, p_w1, 3456, 1152, b1, p_h, 0, 1152, 1);
            S1.c[1] = S1.c[0]; S1.c[2] = S1.c[0]; S1.c[3] = S1.c[0];
            gemm_bf16<<<gridD, 256, SMEM_SZ>>>(S1);

            Cfg4 S2;
            S2.c[0] = mkcfg(p_h, 3456, 1152, p_w2, 3456, 1152, b2, kouts[q], Dd, 1152, 0);
            S2.c[1] = S2.c[0]; S2.c[2] = S2.c[0]; S2.c[3] = S2.c[0];
            gemm_bf16<<<gridD, 256, SMEM_SZ>>>(S2);

            if (q == 0)      rk_c1<<<blkBD, 256>>>(ts, t);
            else if (q == 1) rk_c2<<<blkBD, 256>>>(ts, t);
            else if (q == 2) rk_c3<<<blkBD, 256>>>(ts, t);
            else             rk_c4<<<blkBD, 256>>>(ts, out_x, t);
        }
    }
}

// round 9
// speedup vs baseline: 2.7193x; 1.3394x over previous
#include <cuda_runtime.h>
#include <cuda_bf16.h>
#include <math.h>
#include <stdint.h>

#define Bb   1024
#define Tt   32
#define Xs   128
#define XHd  512
#define AHd  512
#define Dd   1152
#define G3   1536
#define NSTEP 31

typedef __nv_bfloat16 bf16;
typedef __nv_bfloat162 bf162;

// ---------------- fp32 scratch ----------------
__device__ float g_s   [Bb * Dd];
__device__ float g_mask[Bb];
__device__ float g_gia [Bb * G3];
__device__ float g_gha [Bb * G3];
__device__ float g_gix [Bb * G3];
__device__ float g_ghx [Bb * G3];
__device__ float g_k1  [Bb * Dd];
__device__ float g_k2  [Bb * Dd];
__device__ float g_k3  [Bb * Dd];
__device__ float g_k4  [Bb * Dd];
__device__ float g_accb[Bb * Dd];

// ---------------- packed bf16 (A-side [hi|hi|lo], B-side [hi|lo|hi]) -----
__device__ bf16 pk_s  [Bb * 3 * Dd];
__device__ bf16 pk_cat[Bb * 3 * 256];
__device__ bf16 pk_h  [Bb * 3 * Dd];
__device__ bf16 pw_iha[G3 * 3 * 256];
__device__ bf16 pw_hha[G3 * 3 * 512];
__device__ bf16 pw_ihx[G3 * 3 * 128];
__device__ bf16 pw_hhx[G3 * 3 * 512];
__device__ bf16 pw_1  [Dd * 3 * Dd];
__device__ bf16 pw_2  [Dd * 3 * Dd];

__device__ __forceinline__ float sigm(float x) { return 1.0f / (1.0f + expf(-x)); }
__device__ __forceinline__ float splus(float x) { return fmaxf(x, 0.f) + log1pf(expf(-fabsf(x))); }

// A-side pack: [hi | hi | lo]
__device__ __forceinline__ void packA_el(bf16* rowbase, int K, int k, float v)
{
    bf16 hi = __float2bfloat16(v);
    bf16 lo = __float2bfloat16(v - __bfloat162float(hi));
    rowbase[k] = hi; rowbase[K + k] = hi; rowbase[2 * K + k] = lo;
}

__device__ __forceinline__ void cpa16(uint32_t sa, const void* g)
{
    asm volatile("cp.async.cg.shared.global [%0], [%1], 16;\n" :: "r"(sa), "l"(g));
}

#define SSTR 15360
#define SMEM_SZ (4 * SSTR)

// ================= generic batched GEMM (gates) =================
struct Cfg {
    const bf16 *A, *B;
    const float *bias;
    void *Cv;
    int lda, segA, ldb, segB, ldc, K, mode;
};
struct Cfg4 { Cfg c[4]; };

__global__ void __launch_bounds__(256) gemm_bf16(Cfg4 P)
{
    const Cfg cg = P.c[blockIdx.z];
    const bf16* __restrict__ A = cg.A;
    const bf16* __restrict__ B = cg.B;
    const int lda = cg.lda, segA = cg.segA, ldb = cg.ldb, segB = cg.segB;
    const int K = cg.K;
    const int nk = 3 * K / 32;

    extern __shared__ __align__(16) char smraw[];
    const uint32_t su = (uint32_t)__cvta_generic_to_shared(smraw);

    const int tid = threadIdx.x, lane = tid & 31, wid = tid >> 5;
    const int wm = wid >> 2, wn = wid & 3;
    const int bm = blockIdx.y, bn = blockIdx.x;

    const int arow = tid >> 2, ac8 = (tid & 3) * 8;
    const bf16* Ag  = A + (size_t)(bm * 64 + arow) * lda;
    const bf16* Bg0 = B + (size_t)(bn * 128 + arow) * ldb;
    const bf16* Bg1 = B + (size_t)(bn * 128 + 64 + arow) * ldb;

    float acc[2][4][4];
#pragma unroll
    for (int i = 0; i < 2; i++)
#pragma unroll
        for (int j = 0; j < 4; j++)
#pragma unroll
            for (int q = 0; q < 4; q++) acc[i][j][q] = 0.f;

#define ISSUE_G(I)                                                             \
    {                                                                          \
        int kk = (I) * 32;                                                     \
        int seg = (kk >= K) ? ((kk >= 2 * K) ? 2 : 1) : 0;                     \
        int w = kk - seg * K;                                                  \
        int acl = seg * segA + w;                                              \
        int bcl = seg * segB + w;                                              \
        uint32_t sb = su + ((I) & 3) * SSTR;                                   \
        cpa16(sb + arow * 80 + ac8 * 2,               Ag  + acl + ac8);        \
        cpa16(sb + 5120 + arow * 80 + ac8 * 2,        Bg0 + bcl + ac8);        \
        cpa16(sb + 5120 + (64 + arow) * 80 + ac8 * 2, Bg1 + bcl + ac8);        \
        asm volatile("cp.async.commit_group;\n" ::);                           \
    }

    ISSUE_G(0) ISSUE_G(1) ISSUE_G(2)

    for (int i = 0; i < nk; i++) {
        const int st = i & 3;
        const int rem = nk - 1 - i;
        if (rem >= 2)      asm volatile("cp.async.wait_group 2;\n" ::);
        else if (rem == 1) asm volatile("cp.async.wait_group 1;\n" ::);
        else               asm volatile("cp.async.wait_group 0;\n" ::);
        __syncthreads();
        if (i + 3 < nk) ISSUE_G(i + 3)

        const uint32_t sa_base = su + st * SSTR;
        const uint32_t sb_base = sa_base + 5120;
#pragma unroll
        for (int ks = 0; ks < 2; ks++) {
            const int k0 = ks * 16;
            uint32_t a[2][4], b[4][2];
#pragma unroll
            for (int mi = 0; mi < 2; mi++) {
                uint32_t sa = sa_base + (wm * 32 + mi * 16 + (lane & 15)) * 80
                            + (k0 + (lane >> 4) * 8) * 2;
                asm volatile("ldmatrix.sync.aligned.m8n8.x4.shared.b16 {%0,%1,%2,%3}, [%4];"
                             : "=r"(a[mi][0]), "=r"(a[mi][1]), "=r"(a[mi][2]), "=r"(a[mi][3])
                             : "r"(sa));
            }
#pragma unroll
            for (int p = 0; p < 2; p++) {
                uint32_t sb = sb_base
                            + (wn * 32 + (2 * p + ((lane >> 4) & 1)) * 8 + (lane & 7)) * 80
                            + (k0 + ((lane >> 3) & 1) * 8) * 2;
                asm volatile("ldmatrix.sync.aligned.m8n8.x4.shared.b16 {%0,%1,%2,%3}, [%4];"
                             : "=r"(b[2 * p][0]), "=r"(b[2 * p][1]),
                               "=r"(b[2 * p + 1][0]), "=r"(b[2 * p + 1][1])
                             : "r"(sb));
            }
#pragma unroll
            for (int mi = 0; mi < 2; mi++)
#pragma unroll
                for (int ni = 0; ni < 4; ni++) {
                    asm volatile(
                        "mma.sync.aligned.m16n8k16.row.col.f32.bf16.bf16.f32 "
                        "{%0,%1,%2,%3}, {%4,%5,%6,%7}, {%8,%9}, {%0,%1,%2,%3};"
                        : "+f"(acc[mi][ni][0]), "+f"(acc[mi][ni][1]),
                          "+f"(acc[mi][ni][2]), "+f"(acc[mi][ni][3])
                        : "r"(a[mi][0]), "r"(a[mi][1]), "r"(a[mi][2]), "r"(a[mi][3]),
                          "r"(b[ni][0]), "r"(b[ni][1]));
                }
        }
    }
#undef ISSUE_G

    const int rbase = bm * 64 + wm * 32;
    const int cbase = bn * 128 + wn * 32;
    const float* bias = cg.bias;

    float* C = (float*)cg.Cv;
    const int ldc = cg.ldc;
#pragma unroll
    for (int mi = 0; mi < 2; mi++)
#pragma unroll
        for (int ni = 0; ni < 4; ni++) {
            int r0 = rbase + mi * 16 + (lane >> 2);
            int c0 = cbase + ni * 8 + (lane & 3) * 2;
            float b0 = bias[c0], b1 = bias[c0 + 1];
            float2 o0 = make_float2(acc[mi][ni][0] + b0, acc[mi][ni][1] + b1);
            float2 o1 = make_float2(acc[mi][ni][2] + b0, acc[mi][ni][3] + b1);
            *(float2*)(C + (size_t)r0 * ldc + c0) = o0;
            *(float2*)(C + (size_t)(r0 + 8) * ldc + c0) = o1;
        }
}

// ================= specialized D-GEMM (K=1152, nk=108) =================
// Physical layouts are FULL 3K (A [hi|hi|lo], B [hi|lo|hi]) -> identity col map.
// MODE 0: fp32 + bias (ldc). MODE 1: softplus -> packed bf16 [hi|hi|lo] stride 3456.
template <int MODE>
__global__ void __launch_bounds__(256) dgemm(
    const bf16* __restrict__ A, const bf16* __restrict__ B,
    const float* __restrict__ bias, void* __restrict__ Cv, int ldc)
{
    constexpr int K = 1152, LD = 3456, NK = 108;

    extern __shared__ __align__(16) char smraw[];
    const uint32_t su = (uint32_t)__cvta_generic_to_shared(smraw);

    const int tid = threadIdx.x, lane = tid & 31, wid = tid >> 5;
    const int wm = wid >> 2, wn = wid & 3;
    const int bm = blockIdx.y, bn = blockIdx.x;

    const int arow = tid >> 2, ac8 = (tid & 3) * 8;
    const bf16* Ag  = A + (size_t)(bm * 64 + arow) * LD + ac8;
    const bf16* Bg0 = B + (size_t)(bn * 128 + arow) * LD + ac8;
    const bf16* Bg1 = B + (size_t)(bn * 128 + 64 + arow) * LD + ac8;

    float acc[2][4][4];
#pragma unroll
    for (int i = 0; i < 2; i++)
#pragma unroll
        for (int j = 0; j < 4; j++)
#pragma unroll
            for (int q = 0; q < 4; q++) acc[i][j][q] = 0.f;

    // identity column map: col = kk
#define ISSUE_D(I)                                                             \
    {                                                                          \
        int kk = (I) * 32;                                                     \
        uint32_t sb = su + ((I) & 3) * SSTR;                                   \
        cpa16(sb + arow * 80 + ac8 * 2,               Ag  + kk);               \
        cpa16(sb + 5120 + arow * 80 + ac8 * 2,        Bg0 + kk);               \
        cpa16(sb + 5120 + (64 + arow) * 80 + ac8 * 2, Bg1 + kk);               \
        asm volatile("cp.async.commit_group;\n" ::);                           \
    }

#define COMPUTE_D(I)                                                           \
    {                                                                          \
        const uint32_t sa_base = su + ((I) & 3) * SSTR;                        \
        const uint32_t sb_base = sa_base + 5120;                               \
        _Pragma("unroll")                                                      \
        for (int ks = 0; ks < 2; ks++) {                                       \
            const int k0 = ks * 16;                                            \
            uint32_t a[2][4], b[4][2];                                         \
            _Pragma("unroll")                                                  \
            for (int mi = 0; mi < 2; mi++) {                                   \
                uint32_t sa = sa_base + (wm * 32 + mi * 16 + (lane & 15)) * 80 \
                            + (k0 + (lane >> 4) * 8) * 2;                      \
                asm volatile(                                                  \
                    "ldmatrix.sync.aligned.m8n8.x4.shared.b16 {%0,%1,%2,%3}, [%4];" \
                    : "=r"(a[mi][0]), "=r"(a[mi][1]), "=r"(a[mi][2]), "=r"(a[mi][3]) \
                    : "r"(sa));                                                \
            }                                                                  \
            _Pragma("unroll")                                                  \
            for (int p = 0; p < 2; p++) {                                      \
                uint32_t sb = sb_base                                          \
                    + (wn * 32 + (2 * p + ((lane >> 4) & 1)) * 8 + (lane & 7)) * 80 \
                    + (k0 + ((lane >> 3) & 1) * 8) * 2;                        \
                asm volatile(                                                  \
                    "ldmatrix.sync.aligned.m8n8.x4.shared.b16 {%0,%1,%2,%3}, [%4];" \
                    : "=r"(b[2 * p][0]), "=r"(b[2 * p][1]),                    \
                      "=r"(b[2 * p + 1][0]), "=r"(b[2 * p + 1][1])             \
                    : "r"(sb));                                                \
            }                                                                  \
            _Pragma("unroll")                                                  \
            for (int mi = 0; mi < 2; mi++)                                     \
                _Pragma("unroll")                                              \
                for (int ni = 0; ni < 4; ni++) {                               \
                    asm volatile(                                              \
                        "mma.sync.aligned.m16n8k16.row.col.f32.bf16.bf16.f32 " \
                        "{%0,%1,%2,%3}, {%4,%5,%6,%7}, {%8,%9}, {%0,%1,%2,%3};"\
                        : "+f"(acc[mi][ni][0]), "+f"(acc[mi][ni][1]),          \
                          "+f"(acc[mi][ni][2]), "+f"(acc[mi][ni][3])           \
                        : "r"(a[mi][0]), "r"(a[mi][1]), "r"(a[mi][2]), "r"(a[mi][3]), \
                          "r"(b[ni][0]), "r"(b[ni][1]));                       \
                }                                                              \
        }                                                                      \
    }

    ISSUE_D(0) ISSUE_D(1) ISSUE_D(2)

#pragma unroll 4
    for (int i = 0; i < NK - 3; i++) {
        asm volatile("cp.async.wait_group 2;\n" ::);
        __syncthreads();
        ISSUE_D(i + 3)
        COMPUTE_D(i)
    }
    asm volatile("cp.async.wait_group 2;\n" ::);
    __syncthreads();
    COMPUTE_D(NK - 3)
    asm volatile("cp.async.wait_group 1;\n" ::);
    __syncthreads();
    COMPUTE_D(NK - 2)
    asm volatile("cp.async.wait_group 0;\n" ::);
    __syncthreads();
    COMPUTE_D(NK - 1)

#undef ISSUE_D
#undef COMPUTE_D

    const int rbase = bm * 64 + wm * 32;
    const int cbase = bn * 128 + wn * 32;

    if (MODE == 0) {
        float* C = (float*)Cv;
#pragma unroll
        for (int mi = 0; mi < 2; mi++)
#pragma unroll
            for (int ni = 0; ni < 4; ni++) {
                int r0 = rbase + mi * 16 + (lane >> 2);
                int c0 = cbase + ni * 8 + (lane & 3) * 2;
                float b0 = bias[c0], b1 = bias[c0 + 1];
                float2 o0 = make_float2(acc[mi][ni][0] + b0, acc[mi][ni][1] + b1);
                float2 o1 = make_float2(acc[mi][ni][2] + b0, acc[mi][ni][3] + b1);
                *(float2*)(C + (size_t)r0 * ldc + c0) = o0;
                *(float2*)(C + (size_t)(r0 + 8) * ldc + c0) = o1;
            }
    } else {
        bf16* C = (bf16*)Cv;  // packed, row stride 3456
#pragma unroll
        for (int mi = 0; mi < 2; mi++)
#pragma unroll
            for (int ni = 0; ni < 4; ni++) {
                int r0 = rbase + mi * 16 + (lane >> 2);
                int c0 = cbase + ni * 8 + (lane & 3) * 2;
                float b0 = bias[c0], b1 = bias[c0 + 1];
#pragma unroll
                for (int h = 0; h < 2; h++) {
                    float v0 = splus(acc[mi][ni][2 * h + 0] + b0);
                    float v1 = splus(acc[mi][ni][2 * h + 1] + b1);
                    bf16 h0 = __float2bfloat16(v0), h1 = __float2bfloat16(v1);
                    bf16 l0 = __float2bfloat16(v0 - __bfloat162float(h0));
                    bf16 l1 = __float2bfloat16(v1 - __bfloat162float(h1));
                    bf162 hh; hh.x = h0; hh.y = h1;
                    bf162 ll; ll.x = l0; ll.y = l1;
                    bf16* base = C + (size_t)(r0 + 8 * h) * 3456 + c0;
                    *(bf162*)(base)         = hh;
                    *(bf162*)(base + K)     = hh;
                    *(bf162*)(base + 2 * K) = ll;
                }
            }
    }
}

// ---------------- single fused weight pack (B-side: [hi | lo | hi]) ------
__device__ __forceinline__ void packW_el(const float* in, bf16* out, int idx, int K)
{
    int n = idx / K, k = idx % K;
    float v = in[(size_t)n * K + k];
    bf16 hi = __float2bfloat16(v);
    bf16 lo = __float2bfloat16(v - __bfloat162float(hi));
    bf16* o = out + (size_t)n * 3 * K;
    o[k] = hi; o[K + k] = lo; o[2 * K + k] = hi;
}

#define S0 (G3 * 256)
#define S1B (S0 + G3 * 512)
#define S2B (S1B + G3 * 128)
#define S3B (S2B + G3 * 512)
#define S4B (S3B + Dd * Dd)
#define S5B (S4B + Dd * Dd)

__global__ void packAll_k(const float* __restrict__ Wiha, const float* __restrict__ Whha,
                          const float* __restrict__ Wihx, const float* __restrict__ Whhx,
                          const float* __restrict__ W1,   const float* __restrict__ W2)
{
    int idx = blockIdx.x * blockDim.x + threadIdx.x;
    if (idx >= S5B) return;
    if (idx < S0)       packW_el(Wiha, pw_iha, idx,        256);
    else if (idx < S1B) packW_el(Whha, pw_hha, idx - S0,   512);
    else if (idx < S2B) packW_el(Wihx, pw_ihx, idx - S1B,  128);
    else if (idx < S3B) packW_el(Whhx, pw_hhx, idx - S2B,  512);
    else if (idx < S4B) packW_el(W1,   pw_1,   idx - S3B,  Dd);
    else                packW_el(W2,   pw_2,   idx - S4B,  Dd);
}

// ---------------- elementwise (fused state packing) ----------------
__global__ void init_k(const float* __restrict__ x, float* __restrict__ out_x,
                       float* __restrict__ out_za)
{
    int idx = blockIdx.x * blockDim.x + threadIdx.x;
    if (idx >= Bb * Dd) return;
    int b = idx / Dd, j = idx % Dd;
    float v;
    if (j < 1024) {
        v = 0.0f;
        if (j < AHd) out_za[((size_t)b * Tt) * AHd + j] = 0.0f;
    } else {
        v = x[((size_t)b * Tt) * Xs + (j - 1024)];
        out_x[((size_t)b * Tt) * Xs + (j - 1024)] = v;
    }
    g_s[idx] = v;
    packA_el(pk_s + (size_t)b * 3 * Dd, Dd, j, v);
}

__global__ void catmask_k(const float* __restrict__ y, int t)
{
    int b = blockIdx.x;
    int c = threadIdx.x;  // 128
    float yv = y[((size_t)b * Tt + t) * 128 + c];
    float xv = g_s[b * Dd + 1024 + c];
    bf16* rb = pk_cat + (size_t)b * 768;
    packA_el(rb, 256, c, xv);
    packA_el(rb, 256, 128 + c, yv);
    __shared__ float red[128];
    red[c] = yv;
    __syncthreads();
    for (int o = 64; o > 0; o >>= 1) {
        if (c < o) red[c] += red[c + o];
        __syncthreads();
    }
    if (c == 0) g_mask[b] = (red[0] != 0.0f) ? 1.0f : 0.0f;
}

__global__ void gru_k(float* __restrict__ out_za, int t)
{
    int idx = blockIdx.x * blockDim.x + threadIdx.x;
    if (idx >= Bb * 1024) return;
    int b = idx >> 10, j = idx & 1023;
    if (j < XHd) {
        const float* gi = g_gix + (size_t)b * G3;
        const float* gh = g_ghx + (size_t)b * G3;
        float r = sigm(gi[j] + gh[j]);
        float z = sigm(gi[XHd + j] + gh[XHd + j]);
        float n = tanhf(gi[2 * XHd + j] + r * gh[2 * XHd + j]);
        float h = g_s[b * Dd + j];
        float v = (1.0f - z) * n + z * h;
        g_s[b * Dd + j] = v;
        packA_el(pk_s + (size_t)b * 3 * Dd, Dd, j, v);
    } else {
        int ja = j - XHd;
        const float* gi = g_gia + (size_t)b * G3;
        const float* gh = g_gha + (size_t)b * G3;
        float r = sigm(gi[ja] + gh[ja]);
        float z = sigm(gi[AHd + ja] + gh[AHd + ja]);
        float n = tanhf(gi[2 * AHd + ja] + r * gh[2 * AHd + ja]);
        float h = g_s[b * Dd + XHd + ja];
        float hn = (1.0f - z) * n + z * h;
        float v = (g_mask[b] != 0.0f) ? hn : h;
        g_s[b * Dd + XHd + ja] = v;
        packA_el(pk_s + (size_t)b * 3 * Dd, Dd, XHd + ja, v);
        out_za[((size_t)b * Tt + t + 1) * AHd + ja] = v;
    }
}

__global__ void rk_c1(const float* __restrict__ ts, int t)
{
    int i = blockIdx.x * blockDim.x + threadIdx.x;
    if (i >= Bb * Dd) return;
    float dt = ts[t + 1] - ts[t];
    int b = i / Dd, j = i % Dd;
    float v = g_s[i] + (dt * (1.0f / 3.0f)) * g_k1[i];
    packA_el(pk_s + (size_t)b * 3 * Dd, Dd, j, v);
}
__global__ void rk_c2(const float* __restrict__ ts, int t)
{
    int i = blockIdx.x * blockDim.x + threadIdx.x;
    if (i >= Bb * Dd) return;
    float dt = ts[t + 1] - ts[t];
    int b = i / Dd, j = i % Dd;
    float k1 = g_k1[i], k2 = g_k2[i];
    float v = g_s[i] + dt * (k2 - k1 * (1.0f / 3.0f));
    g_accb[i] = k1 + 3.0f * k2;
    packA_el(pk_s + (size_t)b * 3 * Dd, Dd, j, v);
}
__global__ void rk_c3(const float* __restrict__ ts, int t)
{
    int i = blockIdx.x * blockDim.x + threadIdx.x;
    if (i >= Bb * Dd) return;
    float dt = ts[t + 1] - ts[t];
    int b = i / Dd, j = i % Dd;
    float k1 = g_k1[i], k2 = g_k2[i], k3 = g_k3[i];
    float v = g_s[i] + dt * (k1 - k2 + k3);
    g_accb[i] = g_accb[i] + 3.0f * k3;
    packA_el(pk_s + (size_t)b * 3 * Dd, Dd, j, v);
}
__global__ void rk_c4(const float* __restrict__ ts, float* __restrict__ out_x, int t)
{
    int i = blockIdx.x * blockDim.x + threadIdx.x;
    if (i >= Bb * Dd) return;
    float dt = ts[t + 1] - ts[t];
    int b = i / Dd, j = i % Dd;
    float v = g_s[i] + (dt * 0.125f) * (g_accb[i] + g_k4[i]);
    g_s[i] = v;
    packA_el(pk_s + (size_t)b * 3 * Dd, Dd, j, v);
    if (j >= 1024)
        out_x[((size_t)b * Tt + t + 1) * Xs + (j - 1024)] = v;
}

// ---------------- host ----------------
static inline Cfg mkcfg(const bf16* A, int lda, int segA,
                        const bf16* B, int ldb, int segB,
                        const float* bias, void* C, int ldc, int K, int mode)
{
    Cfg c; c.A = A; c.B = B; c.bias = bias; c.Cv = C;
    c.lda = lda; c.segA = segA; c.ldb = ldb; c.segB = segB;
    c.ldc = ldc; c.K = K; c.mode = mode;
    return c;
}

extern "C" void kernel_launch(void* const* d_in, const int* in_sizes, int n_in,
                              void* d_out, int out_size)
{
    const float* x    = (const float*)d_in[0];
    const float* y    = (const float*)d_in[1];
    const float* ts   = (const float*)d_in[2];
    const float* Wiha = (const float*)d_in[3];
    const float* Whha = (const float*)d_in[4];
    const float* biha = (const float*)d_in[5];
    const float* bhha = (const float*)d_in[6];
    const float* Wihx = (const float*)d_in[7];
    const float* Whhx = (const float*)d_in[8];
    const float* bihx = (const float*)d_in[9];
    const float* bhhx = (const float*)d_in[10];
    const float* W1   = (const float*)d_in[11];
    const float* b1   = (const float*)d_in[12];
    const float* W2   = (const float*)d_in[13];
    const float* b2   = (const float*)d_in[14];

    float* out_x  = (float*)d_out;
    float* out_za = out_x + (size_t)Bb * Tt * Xs;

    cudaFuncSetAttribute(gemm_bf16, cudaFuncAttributeMaxDynamicSharedMemorySize, SMEM_SZ);
    cudaFuncSetAttribute(dgemm<0>,  cudaFuncAttributeMaxDynamicSharedMemorySize, SMEM_SZ);
    cudaFuncSetAttribute(dgemm<1>,  cudaFuncAttributeMaxDynamicSharedMemorySize, SMEM_SZ);

    bf16 *p_s, *p_cat, *p_h, *p_iha, *p_hha, *p_ihx, *p_hhx, *p_w1, *p_w2;
    float *pgia, *pgha, *pgix, *pghx, *pk1, *pk2, *pk3, *pk4;
    cudaGetSymbolAddress((void**)&p_s,   pk_s);
    cudaGetSymbolAddress((void**)&p_cat, pk_cat);
    cudaGetSymbolAddress((void**)&p_h,   pk_h);
    cudaGetSymbolAddress((void**)&p_iha, pw_iha);
    cudaGetSymbolAddress((void**)&p_hha, pw_hha);
    cudaGetSymbolAddress((void**)&p_ihx, pw_ihx);
    cudaGetSymbolAddress((void**)&p_hhx, pw_hhx);
    cudaGetSymbolAddress((void**)&p_w1,  pw_1);
    cudaGetSymbolAddress((void**)&p_w2,  pw_2);
    cudaGetSymbolAddress((void**)&pgia,  g_gia);
    cudaGetSymbolAddress((void**)&pgha,  g_gha);
    cudaGetSymbolAddress((void**)&pgix,  g_gix);
    cudaGetSymbolAddress((void**)&pghx,  g_ghx);
    cudaGetSymbolAddress((void**)&pk1,   g_k1);
    cudaGetSymbolAddress((void**)&pk2,   g_k2);
    cudaGetSymbolAddress((void**)&pk3,   g_k3);
    cudaGetSymbolAddress((void**)&pk4,   g_k4);

    packAll_k<<<(S5B + 255) / 256, 256>>>(Wiha, Whha, Wihx, Whhx, W1, W2);

    const int blkBD = (Bb * Dd + 255) / 256;
    const int blkG  = (Bb * 1024 + 255) / 256;

    init_k<<<blkBD, 256>>>(x, out_x, out_za);

    const dim3 gridGate(G3 / 128, Bb / 64, 4);
    const dim3 gridD(Dd / 128, Bb / 64, 1);

    for (int t = 0; t < NSTEP; t++) {
        catmask_k<<<Bb, 128>>>(y, t);

        Cfg4 G;
        G.c[0] = mkcfg(p_cat,        768, 256,  p_iha, 768,  256, biha, pgia, G3, 256, 0);
        G.c[1] = mkcfg(p_s + XHd,   3456, 1152, p_hha, 1536, 512, bhha, pgha, G3, 512, 0);
        G.c[2] = mkcfg(p_s + 1024,  3456, 1152, p_ihx, 384,  128, bihx, pgix, G3, 128, 0);
        G.c[3] = mkcfg(p_s,         3456, 1152, p_hhx, 1536, 512, bhhx, pghx, G3, 512, 0);
        gemm_bf16<<<gridGate, 256, SMEM_SZ>>>(G);

        gru_k<<<blkG, 256>>>(out_za, t);

        float* kouts[4] = {pk1, pk2, pk3, pk4};
        for (int q = 0; q < 4; q++) {
            dgemm<1><<<gridD, 256, SMEM_SZ>>>(p_s, p_w1, b1, p_h, 0);
            dgemm<0><<<gridD, 256, SMEM_SZ>>>(p_h, p_w2, b2, kouts[q], Dd);
            if (q == 0)      rk_c1<<<blkBD, 256>>>(ts, t);
            else if (q == 1) rk_c2<<<blkBD, 256>>>(ts, t);
            else if (q == 2) rk_c3<<<blkBD, 256>>>(ts, t);
            else             rk_c4<<<blkBD, 256>>>(ts, out_x, t);
        }
    }
}